// round 2
// baseline (speedup 1.0000x reference)
#include <cuda_runtime.h>
#include <cuda_bf16.h>
#include <stdint.h>

// Problem constants (from reference): N=100000 nodes, E=1200000 edges, C=64 feats.
#define NN 100000
#define EMAX 1200000
#define C 64

// ---------------- scratch (device globals; no allocation allowed) ----------
__device__ float g_h1[NN * C];        // 25.6 MB
__device__ float g_h2[NN * C];        // 25.6 MB
__device__ float g_dinv[NN];
__device__ int   g_deg[NN];
__device__ int   g_partial[NN];
__device__ int   g_rowptr[NN + 1];
__device__ int   g_cursor[NN];
__device__ int   g_col[EMAX];
__device__ int   g_bsum[128];
__device__ int   g_is64;

// ---------------- dtype probe ----------------------------------------------
// In the int32 view of an int64 edge array, odd words are high words (== 0 for
// values in [0, N)). If data is really int32, odd words are actual node ids
// (random in [0,100000)); 256 consecutive zeros is impossible.
__global__ void k_detect(const int* __restrict__ ei, int E) {
    __shared__ int any_nonzero;
    if (threadIdx.x == 0) any_nonzero = 0;
    __syncthreads();
    int e  = threadIdx.x * (E / 256);       // e < E, so 2e+1 < 2E: safe either way
    int hi = ei[2 * e + 1];
    if (hi != 0) any_nonzero = 1;
    __syncthreads();
    if (threadIdx.x == 0) g_is64 = (any_nonzero == 0);
}

__device__ __forceinline__ int load_idx(const void* eiv, long long pos) {
    if (g_is64) return (int)((const long long*)eiv)[pos];
    return ((const int*)eiv)[pos];
}

// ---------------- preprocessing kernels ------------------------------------
__global__ void k_init_deg(int N) {
    int i = blockIdx.x * blockDim.x + threadIdx.x;
    if (i < N) g_deg[i] = 1;  // self-loop
}

__global__ void k_hist(const void* __restrict__ eiv, int E) {
    int e = blockIdx.x * blockDim.x + threadIdx.x;
    if (e < E) {
        int d = load_idx(eiv, (long long)E + e);
        if ((unsigned)d < (unsigned)NN) atomicAdd(&g_deg[d], 1);
    }
}

#define SCAN_B 1024
__global__ void k_scan1(int N) {
    __shared__ int sh[SCAN_B];
    int i = blockIdx.x * SCAN_B + threadIdx.x;
    int v = (i < N) ? (g_deg[i] - 1) : 0;  // incoming count (exclude self-loop)
    sh[threadIdx.x] = v;
    __syncthreads();
    for (int off = 1; off < SCAN_B; off <<= 1) {
        int t = (threadIdx.x >= off) ? sh[threadIdx.x - off] : 0;
        __syncthreads();
        sh[threadIdx.x] += t;
        __syncthreads();
    }
    if (i < N) g_partial[i] = sh[threadIdx.x] - v;  // exclusive within block
    if (threadIdx.x == SCAN_B - 1) g_bsum[blockIdx.x] = sh[SCAN_B - 1];
}

__global__ void k_scan2(int nb) {
    __shared__ int sh[128];
    int v = (threadIdx.x < nb) ? g_bsum[threadIdx.x] : 0;
    sh[threadIdx.x] = v;
    __syncthreads();
    for (int off = 1; off < 128; off <<= 1) {
        int t = (threadIdx.x >= off) ? sh[threadIdx.x - off] : 0;
        __syncthreads();
        sh[threadIdx.x] += t;
        __syncthreads();
    }
    if (threadIdx.x < nb) g_bsum[threadIdx.x] = sh[threadIdx.x] - v;  // exclusive
}

__global__ void k_scan3(int N) {
    int i = blockIdx.x * blockDim.x + threadIdx.x;
    if (i < N) {
        int r = g_partial[i] + g_bsum[i / SCAN_B];
        g_rowptr[i] = r;
        g_cursor[i] = r;
        g_dinv[i]   = rsqrtf((float)g_deg[i]);
    }
    if (i == N) {
        // total incoming edges = last rowptr + last count
        g_rowptr[N] = g_partial[N - 1] + g_bsum[(N - 1) / SCAN_B] + (g_deg[N - 1] - 1);
    }
}

__global__ void k_scatter(const void* __restrict__ eiv, int E) {
    int e = blockIdx.x * blockDim.x + threadIdx.x;
    if (e < E) {
        int s = load_idx(eiv, e);
        int d = load_idx(eiv, (long long)E + e);
        if ((unsigned)s < (unsigned)NN && (unsigned)d < (unsigned)NN) {
            int p = atomicAdd(&g_cursor[d], 1);
            g_col[p] = s;
        }
    }
}

// ---------------- GEMM: H[N,64] = X[N,64] @ W[64,64] ------------------------
// 256 threads, 64 rows per block. Each thread: 2 rows x 8 cols.
#define XS_STRIDE 68  // pad to avoid bank conflicts on column reads
__global__ void __launch_bounds__(256) k_gemm(const float* __restrict__ X,
                                              const float* __restrict__ W,
                                              float* __restrict__ H, int N) {
    __shared__ float Ws[64 * 64];         // 16 KB
    __shared__ float Xs[64 * XS_STRIDE];  // 17.4 KB
    int tid  = threadIdx.x;
    int row0 = blockIdx.x * 64;

    // load W (1024 float4)
    const float4* W4  = (const float4*)W;
    float4*       Ws4 = (float4*)Ws;
#pragma unroll
    for (int i = 0; i < 4; i++) Ws4[tid + 256 * i] = W4[tid + 256 * i];

    // load X tile (64 rows x 16 float4) into padded smem
    const float4* X4 = (const float4*)(X + (size_t)row0 * C);
#pragma unroll
    for (int i = 0; i < 4; i++) {
        int idx = tid + 256 * i;   // float4 index in unpadded tile
        int r   = idx >> 4;        // row within tile
        int c4  = idx & 15;        // float4 col
        float4 v = make_float4(0.f, 0.f, 0.f, 0.f);
        if (row0 + r < N) v = X4[idx];
        *(float4*)(&Xs[r * XS_STRIDE + c4 * 4]) = v;
    }
    __syncthreads();

    int ty = tid >> 3;   // 0..31
    int tx = tid & 7;    // 0..7
    int r0 = ty, r1 = ty + 32;

    float acc0[8], acc1[8];
#pragma unroll
    for (int j = 0; j < 8; j++) { acc0[j] = 0.f; acc1[j] = 0.f; }

#pragma unroll 4
    for (int k = 0; k < 64; k++) {
        float xv0 = Xs[r0 * XS_STRIDE + k];
        float xv1 = Xs[r1 * XS_STRIDE + k];
        float4 wA = *(const float4*)&Ws[k * 64 + tx * 8];
        float4 wB = *(const float4*)&Ws[k * 64 + tx * 8 + 4];
        acc0[0] += xv0 * wA.x; acc0[1] += xv0 * wA.y;
        acc0[2] += xv0 * wA.z; acc0[3] += xv0 * wA.w;
        acc0[4] += xv0 * wB.x; acc0[5] += xv0 * wB.y;
        acc0[6] += xv0 * wB.z; acc0[7] += xv0 * wB.w;
        acc1[0] += xv1 * wA.x; acc1[1] += xv1 * wA.y;
        acc1[2] += xv1 * wA.z; acc1[3] += xv1 * wA.w;
        acc1[4] += xv1 * wB.x; acc1[5] += xv1 * wB.y;
        acc1[6] += xv1 * wB.z; acc1[7] += xv1 * wB.w;
    }

    int g0 = row0 + r0, g1 = row0 + r1;
    if (g0 < N) {
        float* o = H + (size_t)g0 * C + tx * 8;
        *(float4*)o       = make_float4(acc0[0], acc0[1], acc0[2], acc0[3]);
        *(float4*)(o + 4) = make_float4(acc0[4], acc0[5], acc0[6], acc0[7]);
    }
    if (g1 < N) {
        float* o = H + (size_t)g1 * C + tx * 8;
        *(float4*)o       = make_float4(acc1[0], acc1[1], acc1[2], acc1[3]);
        *(float4*)(o + 4) = make_float4(acc1[4], acc1[5], acc1[6], acc1[7]);
    }
}

// ---------------- aggregation: one warp per node ---------------------------
// out[n] = dinv[n] * sum_{s in in(n)} dinv[s]*H[s] + dinv[n]^2*H[n] + b
__global__ void __launch_bounds__(256) k_agg(const float* __restrict__ H,
                                             const float* __restrict__ bias,
                                             float* __restrict__ out,
                                             int N, int relu) {
    int gid  = blockIdx.x * blockDim.x + threadIdx.x;
    int warp = gid >> 5;
    int lane = gid & 31;
    if (warp >= N) return;
    int n = warp;

    float dn  = g_dinv[n];
    int   beg = g_rowptr[n];
    int   end = g_rowptr[n + 1];

    float a0 = 0.f, a1 = 0.f;
    for (int p = beg; p < end; p += 32) {
        int remaining = end - p;
        int cnt = remaining < 32 ? remaining : 32;
        int   sp = (lane < cnt) ? g_col[p + lane] : 0;
        float dp = (lane < cnt) ? g_dinv[sp] : 0.f;
        for (int j = 0; j < cnt; j++) {
            int   s  = __shfl_sync(0xffffffffu, sp, j);
            float ds = __shfl_sync(0xffffffffu, dp, j);
            const float* hr = H + (size_t)s * C;
            a0 += ds * hr[lane];
            a1 += ds * hr[lane + 32];
        }
    }
    const float* hn = H + (size_t)n * C;
    float r0 = dn * a0 + dn * dn * hn[lane]      + bias[lane];
    float r1 = dn * a1 + dn * dn * hn[lane + 32] + bias[lane + 32];
    if (relu) { r0 = fmaxf(r0, 0.f); r1 = fmaxf(r1, 0.f); }
    out[(size_t)n * C + lane]      = r0;
    out[(size_t)n * C + lane + 32] = r1;
}

// ---------------- launch ----------------------------------------------------
extern "C" void kernel_launch(void* const* d_in, const int* in_sizes, int n_in,
                              void* d_out, int out_size) {
    const float* x   = (const float*)d_in[0];
    const void*  ei  = d_in[1];
    const float* W1  = (const float*)d_in[2];
    const float* b1  = (const float*)d_in[3];
    const float* W2  = (const float*)d_in[4];
    const float* b2  = (const float*)d_in[5];
    float*       out = (float*)d_out;

    int N = in_sizes[0] / C;     // 100000
    int E = in_sizes[1] / 2;     // 1200000

    float* h1;  cudaGetSymbolAddress((void**)&h1, g_h1);
    float* h2;  cudaGetSymbolAddress((void**)&h2, g_h2);

    // preprocessing: dtype probe, degree -> dinv, CSR by dst
    k_detect<<<1, 256>>>((const int*)ei, E);
    k_init_deg<<<(N + 255) / 256, 256>>>(N);
    k_hist<<<(E + 255) / 256, 256>>>(ei, E);
    int nb = (N + SCAN_B - 1) / SCAN_B;          // 98 <= 128
    k_scan1<<<nb, SCAN_B>>>(N);
    k_scan2<<<1, 128>>>(nb);
    k_scan3<<<(N + 256) / 256, 256>>>(N);
    k_scatter<<<(E + 255) / 256, 256>>>(ei, E);

    int gemm_blocks = (N + 63) / 64;
    int agg_blocks  = (N + 7) / 8;               // 8 warps (nodes) per block

    // layer 1
    k_gemm<<<gemm_blocks, 256>>>(x, W1, h1, N);
    k_agg<<<agg_blocks, 256>>>(h1, b1, h2, N, 1);
    // layer 2
    k_gemm<<<gemm_blocks, 256>>>(h2, W2, h1, N);
    k_agg<<<agg_blocks, 256>>>(h1, b2, out, N, 0);
}

// round 3
// speedup vs baseline: 1.0509x; 1.0509x over previous
#include <cuda_runtime.h>
#include <cuda_bf16.h>
#include <stdint.h>

#define NN 100000
#define EMAX 1200000
#define C 64

// ---------------- scratch (device globals; no allocation allowed) ----------
__device__ float g_h1[NN * C];
__device__ float g_h2[NN * C];
__device__ float g_dinv[NN];
__device__ int   g_deg[NN];        // incoming-edge count (self-loop excluded)
__device__ int   g_partial[NN];
__device__ int   g_rowptr[NN + 1];
__device__ int   g_cursor[NN];
__device__ int   g_col[EMAX];
__device__ int   g_bsum[128];
__device__ int   g_is64;

// ---------------- dtype probe ----------------------------------------------
__global__ void k_detect(const int* __restrict__ ei, int E) {
    __shared__ int any_nonzero;
    if (threadIdx.x == 0) any_nonzero = 0;
    __syncthreads();
    int e  = threadIdx.x * (E / 256);
    int hi = ei[2 * e + 1];
    if (hi != 0) any_nonzero = 1;
    __syncthreads();
    if (threadIdx.x == 0) g_is64 = (any_nonzero == 0);
}

__device__ __forceinline__ int load_idx(const void* eiv, long long pos) {
    if (g_is64) return (int)((const long long*)eiv)[pos];
    return ((const int*)eiv)[pos];
}

// ---------------- preprocessing ---------------------------------------------
__global__ void k_hist(const void* __restrict__ eiv, int E) {
    int e = blockIdx.x * blockDim.x + threadIdx.x;
    if (e < E) {
        int d = load_idx(eiv, (long long)E + e);
        if ((unsigned)d < (unsigned)NN) atomicAdd(&g_deg[d], 1);
    }
}

#define SCAN_B 1024
__global__ void __launch_bounds__(SCAN_B) k_scan1(int N) {
    __shared__ int warpsum[32];
    int i    = blockIdx.x * SCAN_B + threadIdx.x;
    int lane = threadIdx.x & 31;
    int wid  = threadIdx.x >> 5;
    int v = (i < N) ? g_deg[i] : 0;
    int x = v;
#pragma unroll
    for (int o = 1; o < 32; o <<= 1) {
        int t = __shfl_up_sync(0xffffffffu, x, o);
        if (lane >= o) x += t;
    }
    if (lane == 31) warpsum[wid] = x;
    __syncthreads();
    if (wid == 0) {
        int s = warpsum[lane];
#pragma unroll
        for (int o = 1; o < 32; o <<= 1) {
            int t = __shfl_up_sync(0xffffffffu, s, o);
            if (lane >= o) s += t;
        }
        warpsum[lane] = s;
    }
    __syncthreads();
    int excl = x - v + (wid ? warpsum[wid - 1] : 0);
    if (i < N) g_partial[i] = excl;
    if (threadIdx.x == SCAN_B - 1) g_bsum[blockIdx.x] = excl + v;
}

__global__ void k_scan2(int nb) {
    __shared__ int sh[128];
    int v = (threadIdx.x < nb) ? g_bsum[threadIdx.x] : 0;
    sh[threadIdx.x] = v;
    __syncthreads();
    for (int off = 1; off < 128; off <<= 1) {
        int t = (threadIdx.x >= off) ? sh[threadIdx.x - off] : 0;
        __syncthreads();
        sh[threadIdx.x] += t;
        __syncthreads();
    }
    if (threadIdx.x < nb) g_bsum[threadIdx.x] = sh[threadIdx.x] - v;
}

__global__ void k_scan3(int N) {
    int i = blockIdx.x * blockDim.x + threadIdx.x;
    if (i < N) {
        int r = g_partial[i] + g_bsum[i / SCAN_B];
        g_rowptr[i] = r;
        g_cursor[i] = r;
        g_dinv[i]   = rsqrtf((float)(g_deg[i] + 1));  // +1 self-loop
    }
    if (i == N)
        g_rowptr[N] = g_partial[N - 1] + g_bsum[(N - 1) / SCAN_B] + g_deg[N - 1];
}

__global__ void k_scatter(const void* __restrict__ eiv, int E) {
    int e = blockIdx.x * blockDim.x + threadIdx.x;
    if (e < E) {
        int s = load_idx(eiv, e);
        int d = load_idx(eiv, (long long)E + e);
        if ((unsigned)s < (unsigned)NN && (unsigned)d < (unsigned)NN) {
            int p = atomicAdd(&g_cursor[d], 1);
            g_col[p] = s;
        }
    }
}

// ---------------- packed f32x2 helpers (sm_103a FFMA2 via PTX) --------------
__device__ __forceinline__ unsigned long long pack2(float x) {
    unsigned long long r;
    asm("mov.b64 %0, {%1, %1};" : "=l"(r) : "f"(x));
    return r;
}
__device__ __forceinline__ void fma2(unsigned long long& d,
                                     unsigned long long a,
                                     unsigned long long b) {
    asm("fma.rn.f32x2 %0, %1, %2, %0;" : "+l"(d) : "l"(a), "l"(b));
}
__device__ __forceinline__ float2 unpack2(unsigned long long v) {
    float lo, hi;
    asm("mov.b64 {%0, %1}, %2;" : "=f"(lo), "=f"(hi) : "l"(v));
    return make_float2(lo, hi);
}

// ---------------- GEMM: H[N,64] = X[N,64] @ W[64,64] ------------------------
#define XS_STRIDE 68
__global__ void __launch_bounds__(256) k_gemm(const float* __restrict__ X,
                                              const float* __restrict__ W,
                                              float* __restrict__ H, int N) {
    __shared__ float Ws[64 * 64];
    __shared__ float Xs[64 * XS_STRIDE];
    int tid  = threadIdx.x;
    int row0 = blockIdx.x * 64;

    const float4* W4  = (const float4*)W;
    float4*       Ws4 = (float4*)Ws;
#pragma unroll
    for (int i = 0; i < 4; i++) Ws4[tid + 256 * i] = W4[tid + 256 * i];

    const float4* X4 = (const float4*)(X + (size_t)row0 * C);
#pragma unroll
    for (int i = 0; i < 4; i++) {
        int idx = tid + 256 * i;
        int r   = idx >> 4;
        int c4  = idx & 15;
        float4 v = make_float4(0.f, 0.f, 0.f, 0.f);
        if (row0 + r < N) v = X4[idx];
        *(float4*)(&Xs[r * XS_STRIDE + c4 * 4]) = v;
    }
    __syncthreads();

    int ty = tid >> 3;   // 0..31
    int tx = tid & 7;    // 0..7
    int r0 = ty, r1 = ty + 32;

    unsigned long long acc0[4] = {0, 0, 0, 0};   // f32x2 zeros
    unsigned long long acc1[4] = {0, 0, 0, 0};

#pragma unroll 8
    for (int k = 0; k < 64; k++) {
        unsigned long long xv0 = pack2(Xs[r0 * XS_STRIDE + k]);
        unsigned long long xv1 = pack2(Xs[r1 * XS_STRIDE + k]);
        // W row k, cols tx*8 .. tx*8+7 as 4 pre-packed f32x2 values
        const ulonglong2* wp = (const ulonglong2*)&Ws[k * 64 + tx * 8];
        ulonglong2 wa = wp[0];
        ulonglong2 wb = wp[1];
        fma2(acc0[0], xv0, wa.x); fma2(acc0[1], xv0, wa.y);
        fma2(acc0[2], xv0, wb.x); fma2(acc0[3], xv0, wb.y);
        fma2(acc1[0], xv1, wa.x); fma2(acc1[1], xv1, wa.y);
        fma2(acc1[2], xv1, wb.x); fma2(acc1[3], xv1, wb.y);
    }

    int g0 = row0 + r0, g1 = row0 + r1;
    if (g0 < N) {
        float2 a = unpack2(acc0[0]), b = unpack2(acc0[1]);
        float2 c = unpack2(acc0[2]), d = unpack2(acc0[3]);
        float* o = H + (size_t)g0 * C + tx * 8;
        *(float4*)o       = make_float4(a.x, a.y, b.x, b.y);
        *(float4*)(o + 4) = make_float4(c.x, c.y, d.x, d.y);
    }
    if (g1 < N) {
        float2 a = unpack2(acc1[0]), b = unpack2(acc1[1]);
        float2 c = unpack2(acc1[2]), d = unpack2(acc1[3]);
        float* o = H + (size_t)g1 * C + tx * 8;
        *(float4*)o       = make_float4(a.x, a.y, b.x, b.y);
        *(float4*)(o + 4) = make_float4(c.x, c.y, d.x, d.y);
    }
}

// ---------------- aggregation: one warp per node, half-warp per edge --------
// lanes 0-15 handle even edges, lanes 16-31 odd edges; each half-warp reads a
// full 256B row via float4 (LDG.128). Tail is branch-free: padded lanes carry
// dp=0 so their contribution is zero (the row-0 load is harmless).
__global__ void __launch_bounds__(256) k_agg(const float* __restrict__ H,
                                             const float* __restrict__ bias,
                                             float* __restrict__ out,
                                             int N, int relu) {
    int gid  = blockIdx.x * blockDim.x + threadIdx.x;
    int n    = gid >> 5;
    int lane = gid & 31;
    if (n >= N) return;
    int grp = lane >> 4;        // 0 or 1
    int c4  = (lane & 15) * 4;  // starting column of my float4

    float dn  = g_dinv[n];
    int   beg = g_rowptr[n];
    int   end = g_rowptr[n + 1];

    float4 acc = make_float4(0.f, 0.f, 0.f, 0.f);
    for (int p = beg; p < end; p += 32) {
        int remaining = end - p;
        int cnt = remaining < 32 ? remaining : 32;
        int   sp = (lane < cnt) ? g_col[p + lane] : 0;
        float dp = (lane < cnt) ? g_dinv[sp] : 0.f;
        int pairs = (cnt + 1) >> 1;
#pragma unroll 4
        for (int j = 0; j < pairs; j++) {
            int   idx = 2 * j + grp;
            int   s   = __shfl_sync(0xffffffffu, sp, idx);
            float ds  = __shfl_sync(0xffffffffu, dp, idx);
            float4 v  = *(const float4*)(H + (size_t)s * C + c4);
            acc.x += ds * v.x; acc.y += ds * v.y;
            acc.z += ds * v.z; acc.w += ds * v.w;
        }
    }
    // combine the two half-warps
    acc.x += __shfl_xor_sync(0xffffffffu, acc.x, 16);
    acc.y += __shfl_xor_sync(0xffffffffu, acc.y, 16);
    acc.z += __shfl_xor_sync(0xffffffffu, acc.z, 16);
    acc.w += __shfl_xor_sync(0xffffffffu, acc.w, 16);

    if (lane < 16) {
        float dn2 = dn * dn;
        float4 hv = *(const float4*)(H + (size_t)n * C + c4);
        float4 bv = *(const float4*)(bias + c4);
        float4 r;
        r.x = dn * acc.x + dn2 * hv.x + bv.x;
        r.y = dn * acc.y + dn2 * hv.y + bv.y;
        r.z = dn * acc.z + dn2 * hv.z + bv.z;
        r.w = dn * acc.w + dn2 * hv.w + bv.w;
        if (relu) {
            r.x = fmaxf(r.x, 0.f); r.y = fmaxf(r.y, 0.f);
            r.z = fmaxf(r.z, 0.f); r.w = fmaxf(r.w, 0.f);
        }
        *(float4*)(out + (size_t)n * C + c4) = r;
    }
}

// ---------------- launch ----------------------------------------------------
extern "C" void kernel_launch(void* const* d_in, const int* in_sizes, int n_in,
                              void* d_out, int out_size) {
    const float* x   = (const float*)d_in[0];
    const void*  ei  = d_in[1];
    const float* W1  = (const float*)d_in[2];
    const float* b1  = (const float*)d_in[3];
    const float* W2  = (const float*)d_in[4];
    const float* b2  = (const float*)d_in[5];
    float*       out = (float*)d_out;

    int N = in_sizes[0] / C;     // 100000
    int E = in_sizes[1] / 2;     // 1200000

    float* h1;   cudaGetSymbolAddress((void**)&h1, g_h1);
    float* h2;   cudaGetSymbolAddress((void**)&h2, g_h2);
    int*   degp; cudaGetSymbolAddress((void**)&degp, g_deg);

    // preprocessing: dtype probe, degree -> dinv, CSR by dst
    k_detect<<<1, 256>>>((const int*)ei, E);
    cudaMemsetAsync(degp, 0, (size_t)N * sizeof(int));
    k_hist<<<(E + 255) / 256, 256>>>(ei, E);
    int nb = (N + SCAN_B - 1) / SCAN_B;
    k_scan1<<<nb, SCAN_B>>>(N);
    k_scan2<<<1, 128>>>(nb);
    k_scan3<<<(N + 256) / 256, 256>>>(N);
    k_scatter<<<(E + 255) / 256, 256>>>(ei, E);

    int gemm_blocks = (N + 63) / 64;
    int agg_blocks  = (N + 7) / 8;

    // layer 1
    k_gemm<<<gemm_blocks, 256>>>(x, W1, h1, N);
    k_agg<<<agg_blocks, 256>>>(h1, b1, h2, N, 1);
    // layer 2
    k_gemm<<<gemm_blocks, 256>>>(h2, W2, h1, N);
    k_agg<<<agg_blocks, 256>>>(h1, b2, out, N, 0);
}

// round 4
// speedup vs baseline: 1.0598x; 1.0085x over previous
#include <cuda_runtime.h>
#include <cuda_bf16.h>
#include <stdint.h>

#define NN 100000
#define EMAX 1200000
#define C 64

// ---------------- scratch (device globals; no allocation allowed) ----------
__device__ float g_h1[NN * C];
__device__ float g_h2[NN * C];
__device__ float g_dinv[NN];
__device__ int   g_deg[NN];        // incoming-edge count (self-loop excluded)
__device__ int   g_partial[NN];
__device__ int   g_rowptr[NN + 1];
__device__ int   g_cursor[NN];
__device__ int   g_col[EMAX];
__device__ int   g_bsum[128];
__device__ int   g_is64;

// ---------------- init: zero degrees + dtype probe (fused) ------------------
// In the int32 view of an int64 edge array, odd words are the high words
// (== 0 for ids in [0, N)). Real int32 data has random ids there.
__global__ void k_init(const int* __restrict__ ei, int E, int N) {
    int i = blockIdx.x * blockDim.x + threadIdx.x;
    if (i < N) g_deg[i] = 0;
    if (blockIdx.x == 0) {
        __shared__ int any_nonzero;
        if (threadIdx.x == 0) any_nonzero = 0;
        __syncthreads();
        int e = threadIdx.x * (E / 256);
        if (ei[2 * e + 1] != 0) any_nonzero = 1;
        __syncthreads();
        if (threadIdx.x == 0) g_is64 = (any_nonzero == 0);
    }
}

__device__ __forceinline__ int load_idx(const void* eiv, long long pos) {
    if (g_is64) return (int)((const long long*)eiv)[pos];
    return ((const int*)eiv)[pos];
}

// ---------------- preprocessing ---------------------------------------------
__global__ void k_hist(const void* __restrict__ eiv, int E) {
    int e = blockIdx.x * blockDim.x + threadIdx.x;
    if (e < E) {
        int d = load_idx(eiv, (long long)E + e);
        if ((unsigned)d < (unsigned)NN) atomicAdd(&g_deg[d], 1);
    }
}

#define SCAN_B 1024
__global__ void __launch_bounds__(SCAN_B) k_scan1(int N) {
    __shared__ int warpsum[32];
    int i    = blockIdx.x * SCAN_B + threadIdx.x;
    int lane = threadIdx.x & 31;
    int wid  = threadIdx.x >> 5;
    int v = (i < N) ? g_deg[i] : 0;
    int x = v;
#pragma unroll
    for (int o = 1; o < 32; o <<= 1) {
        int t = __shfl_up_sync(0xffffffffu, x, o);
        if (lane >= o) x += t;
    }
    if (lane == 31) warpsum[wid] = x;
    __syncthreads();
    if (wid == 0) {
        int s = warpsum[lane];
#pragma unroll
        for (int o = 1; o < 32; o <<= 1) {
            int t = __shfl_up_sync(0xffffffffu, s, o);
            if (lane >= o) s += t;
        }
        warpsum[lane] = s;
    }
    __syncthreads();
    int excl = x - v + (wid ? warpsum[wid - 1] : 0);
    if (i < N) g_partial[i] = excl;
    if (threadIdx.x == SCAN_B - 1) g_bsum[blockIdx.x] = excl + v;
}

// scan3 with inlined bsum-prefix: every 256 indices of this block live in ONE
// 1024-wide scan1 block, so the whole block needs a single prefix value.
__global__ void __launch_bounds__(256) k_scan3(int N, int nb) {
    __shared__ int sh[16];
    int t = threadIdx.x;
    int k = (blockIdx.x * 256) / SCAN_B;     // which scan1 block we're inside
    int vk = (t < k)  ? g_bsum[t] : 0;       // prefix contribution
    int va = (t < nb) ? g_bsum[t] : 0;       // total (for rowptr[N])
#pragma unroll
    for (int o = 16; o; o >>= 1) {
        vk += __shfl_xor_sync(0xffffffffu, vk, o);
        va += __shfl_xor_sync(0xffffffffu, va, o);
    }
    if ((t & 31) == 0) { sh[t >> 5] = vk; sh[8 + (t >> 5)] = va; }
    __syncthreads();
    if (t == 0) {
        int a = 0, b = 0;
#pragma unroll
        for (int w = 0; w < 8; w++) { a += sh[w]; b += sh[8 + w]; }
        sh[0] = a; sh[8] = b;
    }
    __syncthreads();
    int pre = sh[0], tot = sh[8];
    int i = blockIdx.x * 256 + t;
    if (i < N) {
        int r = g_partial[i] + pre;
        g_rowptr[i] = r;
        g_cursor[i] = r;
        g_dinv[i]   = rsqrtf((float)(g_deg[i] + 1));  // +1 self-loop
    }
    if (i == N) g_rowptr[N] = tot;
}

__global__ void k_scatter(const void* __restrict__ eiv, int E) {
    int e = blockIdx.x * blockDim.x + threadIdx.x;
    if (e < E) {
        int s = load_idx(eiv, e);
        int d = load_idx(eiv, (long long)E + e);
        if ((unsigned)s < (unsigned)NN && (unsigned)d < (unsigned)NN) {
            int p = atomicAdd(&g_cursor[d], 1);
            g_col[p] = s;
        }
    }
}

// ---------------- packed f32x2 helpers (sm_103a FFMA2 via PTX) --------------
__device__ __forceinline__ unsigned long long pack2(float x) {
    unsigned long long r;
    asm("mov.b64 %0, {%1, %1};" : "=l"(r) : "f"(x));
    return r;
}
__device__ __forceinline__ void fma2(unsigned long long& d,
                                     unsigned long long a,
                                     unsigned long long b) {
    asm("fma.rn.f32x2 %0, %1, %2, %0;" : "+l"(d) : "l"(a), "l"(b));
}
__device__ __forceinline__ float2 unpack2(unsigned long long v) {
    float lo, hi;
    asm("mov.b64 {%0, %1}, %2;" : "=f"(lo), "=f"(hi) : "l"(v));
    return make_float2(lo, hi);
}

// ---------------- GEMM + dinv prescale: H[n] = dinv[n] * (X[n] @ W) ---------
#define XS_STRIDE 68
__global__ void __launch_bounds__(256) k_gemm(const float* __restrict__ X,
                                              const float* __restrict__ W,
                                              float* __restrict__ H, int N) {
    __shared__ float Ws[64 * 64];
    __shared__ float Xs[64 * XS_STRIDE];
    int tid  = threadIdx.x;
    int row0 = blockIdx.x * 64;

    const float4* W4  = (const float4*)W;
    float4*       Ws4 = (float4*)Ws;
#pragma unroll
    for (int i = 0; i < 4; i++) Ws4[tid + 256 * i] = W4[tid + 256 * i];

    const float4* X4 = (const float4*)(X + (size_t)row0 * C);
#pragma unroll
    for (int i = 0; i < 4; i++) {
        int idx = tid + 256 * i;
        int r   = idx >> 4;
        int c4  = idx & 15;
        float4 v = make_float4(0.f, 0.f, 0.f, 0.f);
        if (row0 + r < N) v = X4[idx];
        *(float4*)(&Xs[r * XS_STRIDE + c4 * 4]) = v;
    }
    __syncthreads();

    int ty = tid >> 3;   // 0..31
    int tx = tid & 7;    // 0..7
    int r0 = ty, r1 = ty + 32;

    unsigned long long acc0[4] = {0, 0, 0, 0};
    unsigned long long acc1[4] = {0, 0, 0, 0};

#pragma unroll 8
    for (int k = 0; k < 64; k++) {
        unsigned long long xv0 = pack2(Xs[r0 * XS_STRIDE + k]);
        unsigned long long xv1 = pack2(Xs[r1 * XS_STRIDE + k]);
        const ulonglong2* wp = (const ulonglong2*)&Ws[k * 64 + tx * 8];
        ulonglong2 wa = wp[0];
        ulonglong2 wb = wp[1];
        fma2(acc0[0], xv0, wa.x); fma2(acc0[1], xv0, wa.y);
        fma2(acc0[2], xv0, wb.x); fma2(acc0[3], xv0, wb.y);
        fma2(acc1[0], xv1, wa.x); fma2(acc1[1], xv1, wa.y);
        fma2(acc1[2], xv1, wb.x); fma2(acc1[3], xv1, wb.y);
    }

    int g0 = row0 + r0, g1 = row0 + r1;
    if (g0 < N) {
        float dn = g_dinv[g0];
        float2 a = unpack2(acc0[0]), b = unpack2(acc0[1]);
        float2 c = unpack2(acc0[2]), d = unpack2(acc0[3]);
        float* o = H + (size_t)g0 * C + tx * 8;
        *(float4*)o       = make_float4(dn * a.x, dn * a.y, dn * b.x, dn * b.y);
        *(float4*)(o + 4) = make_float4(dn * c.x, dn * c.y, dn * d.x, dn * d.y);
    }
    if (g1 < N) {
        float dn = g_dinv[g1];
        float2 a = unpack2(acc1[0]), b = unpack2(acc1[1]);
        float2 c = unpack2(acc1[2]), d = unpack2(acc1[3]);
        float* o = H + (size_t)g1 * C + tx * 8;
        *(float4*)o       = make_float4(dn * a.x, dn * a.y, dn * b.x, dn * b.y);
        *(float4*)(o + 4) = make_float4(dn * c.x, dn * c.y, dn * d.x, dn * d.y);
    }
}

// ---------------- aggregation on prescaled H --------------------------------
// out[n] = dinv[n] * (sum_{s in in(n)} H[s] + H[n]) + b  (H already dinv-scaled)
__global__ void __launch_bounds__(256) k_agg(const float* __restrict__ H,
                                             const float* __restrict__ bias,
                                             float* __restrict__ out,
                                             int N, int relu) {
    int gid  = blockIdx.x * blockDim.x + threadIdx.x;
    int n    = gid >> 5;
    int lane = gid & 31;
    if (n >= N) return;
    int grp = lane >> 4;        // half-warp id
    int c4  = (lane & 15) * 4;  // my float4 column

    int beg = g_rowptr[n];
    int end = g_rowptr[n + 1];

    float4 acc = make_float4(0.f, 0.f, 0.f, 0.f);
    for (int p = beg; p < end; p += 32) {
        int remaining = end - p;
        int cnt = remaining < 32 ? remaining : 32;
        int sp = (lane < cnt) ? g_col[p + lane] : 0;
        int pairs = (cnt + 1) >> 1;
#pragma unroll 4
        for (int j = 0; j < pairs; j++) {
            int   idx = 2 * j + grp;
            int   s   = __shfl_sync(0xffffffffu, sp, idx);
            float m   = (idx < cnt) ? 1.f : 0.f;   // kill padded edge
            float4 v  = *(const float4*)(H + (size_t)s * C + c4);
            acc.x += m * v.x; acc.y += m * v.y;
            acc.z += m * v.z; acc.w += m * v.w;
        }
    }
    acc.x += __shfl_xor_sync(0xffffffffu, acc.x, 16);
    acc.y += __shfl_xor_sync(0xffffffffu, acc.y, 16);
    acc.z += __shfl_xor_sync(0xffffffffu, acc.z, 16);
    acc.w += __shfl_xor_sync(0xffffffffu, acc.w, 16);

    if (lane < 16) {
        float dn  = g_dinv[n];
        float4 hv = *(const float4*)(H + (size_t)n * C + c4);
        float4 bv = *(const float4*)(bias + c4);
        float4 r;
        r.x = dn * (acc.x + hv.x) + bv.x;
        r.y = dn * (acc.y + hv.y) + bv.y;
        r.z = dn * (acc.z + hv.z) + bv.z;
        r.w = dn * (acc.w + hv.w) + bv.w;
        if (relu) {
            r.x = fmaxf(r.x, 0.f); r.y = fmaxf(r.y, 0.f);
            r.z = fmaxf(r.z, 0.f); r.w = fmaxf(r.w, 0.f);
        }
        *(float4*)(out + (size_t)n * C + c4) = r;
    }
}

// ---------------- launch ----------------------------------------------------
extern "C" void kernel_launch(void* const* d_in, const int* in_sizes, int n_in,
                              void* d_out, int out_size) {
    const float* x   = (const float*)d_in[0];
    const void*  ei  = d_in[1];
    const float* W1  = (const float*)d_in[2];
    const float* b1  = (const float*)d_in[3];
    const float* W2  = (const float*)d_in[4];
    const float* b2  = (const float*)d_in[5];
    float*       out = (float*)d_out;

    int N = in_sizes[0] / C;     // 100000
    int E = in_sizes[1] / 2;     // 1200000

    float* h1; cudaGetSymbolAddress((void**)&h1, g_h1);
    float* h2; cudaGetSymbolAddress((void**)&h2, g_h2);

    int nb = (N + SCAN_B - 1) / SCAN_B;          // 98
    int nblk = (N + 255) / 256;                  // 391

    // preprocessing: 5 launches
    k_init<<<nblk, 256>>>((const int*)ei, E, N);
    k_hist<<<(E + 255) / 256, 256>>>(ei, E);
    k_scan1<<<nb, SCAN_B>>>(N);
    k_scan3<<<nblk + 1, 256>>>(N, nb);           // +1 block to cover i==N
    k_scatter<<<(E + 255) / 256, 256>>>(ei, E);

    int gemm_blocks = (N + 63) / 64;
    int agg_blocks  = (N + 7) / 8;

    // layer 1
    k_gemm<<<gemm_blocks, 256>>>(x, W1, h1, N);
    k_agg<<<agg_blocks, 256>>>(h1, b1, h2, N, 1);
    // layer 2
    k_gemm<<<gemm_blocks, 256>>>(h2, W2, h1, N);
    k_agg<<<agg_blocks, 256>>>(h1, b2, out, N, 0);
}

// round 5
// speedup vs baseline: 1.0894x; 1.0279x over previous
#include <cuda_runtime.h>
#include <cuda_fp16.h>
#include <stdint.h>

#define NN 100000
#define EMAX 1200000
#define C 64

// ---------------- scratch (device globals; no allocation allowed) ----------
__device__ __half g_h1[NN * C];    // 12.8 MB, prescaled hidden (fp16)
__device__ float  g_h2[NN * C];    // 25.6 MB, fp32 (GEMM2 input)
__device__ float  g_dinv[NN];
__device__ int    g_deg[NN];
__device__ int    g_partial[NN];
__device__ int    g_rowptr[NN + 1];
__device__ int    g_cursor[NN];
__device__ int    g_col[EMAX];
__device__ int    g_bsum[128];
__device__ int    g_is64;

// ---------------- init: zero degrees + dtype probe (fused) ------------------
__global__ void k_init(const int* __restrict__ ei, int E, int N) {
    int i = blockIdx.x * blockDim.x + threadIdx.x;
    if (i < N) g_deg[i] = 0;
    if (blockIdx.x == 0) {
        __shared__ int any_nonzero;
        if (threadIdx.x == 0) any_nonzero = 0;
        __syncthreads();
        int e = threadIdx.x * (E / 256);
        if (ei[2 * e + 1] != 0) any_nonzero = 1;
        __syncthreads();
        if (threadIdx.x == 0) g_is64 = (any_nonzero == 0);
    }
}

__device__ __forceinline__ int load_idx(const void* eiv, long long pos) {
    if (g_is64) return (int)((const long long*)eiv)[pos];
    return ((const int*)eiv)[pos];
}

// ---------------- preprocessing ---------------------------------------------
__global__ void k_hist(const void* __restrict__ eiv, int E) {
    int e = blockIdx.x * blockDim.x + threadIdx.x;
    if (e < E) {
        int d = load_idx(eiv, (long long)E + e);
        if ((unsigned)d < (unsigned)NN) atomicAdd(&g_deg[d], 1);
    }
}

#define SCAN_B 1024
__global__ void __launch_bounds__(SCAN_B) k_scan1(int N) {
    __shared__ int warpsum[32];
    int i    = blockIdx.x * SCAN_B + threadIdx.x;
    int lane = threadIdx.x & 31;
    int wid  = threadIdx.x >> 5;
    int v = (i < N) ? g_deg[i] : 0;
    int x = v;
#pragma unroll
    for (int o = 1; o < 32; o <<= 1) {
        int t = __shfl_up_sync(0xffffffffu, x, o);
        if (lane >= o) x += t;
    }
    if (lane == 31) warpsum[wid] = x;
    __syncthreads();
    if (wid == 0) {
        int s = warpsum[lane];
#pragma unroll
        for (int o = 1; o < 32; o <<= 1) {
            int t = __shfl_up_sync(0xffffffffu, s, o);
            if (lane >= o) s += t;
        }
        warpsum[lane] = s;
    }
    __syncthreads();
    int excl = x - v + (wid ? warpsum[wid - 1] : 0);
    if (i < N) g_partial[i] = excl;
    if (threadIdx.x == SCAN_B - 1) g_bsum[blockIdx.x] = excl + v;
}

__global__ void __launch_bounds__(256) k_scan3(int N, int nb) {
    __shared__ int sh[16];
    int t = threadIdx.x;
    int k = (blockIdx.x * 256) / SCAN_B;
    int vk = (t < k)  ? g_bsum[t] : 0;
    int va = (t < nb) ? g_bsum[t] : 0;
#pragma unroll
    for (int o = 16; o; o >>= 1) {
        vk += __shfl_xor_sync(0xffffffffu, vk, o);
        va += __shfl_xor_sync(0xffffffffu, va, o);
    }
    if ((t & 31) == 0) { sh[t >> 5] = vk; sh[8 + (t >> 5)] = va; }
    __syncthreads();
    if (t == 0) {
        int a = 0, b = 0;
#pragma unroll
        for (int w = 0; w < 8; w++) { a += sh[w]; b += sh[8 + w]; }
        sh[0] = a; sh[8] = b;
    }
    __syncthreads();
    int pre = sh[0], tot = sh[8];
    int i = blockIdx.x * 256 + t;
    if (i < N) {
        int r = g_partial[i] + pre;
        g_rowptr[i] = r;
        g_cursor[i] = r;
        g_dinv[i]   = rsqrtf((float)(g_deg[i] + 1));
    }
    if (i == N) g_rowptr[N] = tot;
}

__device__ __forceinline__ void scatter_body(const void* eiv, int E, int bid) {
    int e = bid * 256 + threadIdx.x;
    if (e < E) {
        int s = load_idx(eiv, e);
        int d = load_idx(eiv, (long long)E + e);
        if ((unsigned)s < (unsigned)NN && (unsigned)d < (unsigned)NN) {
            int p = atomicAdd(&g_cursor[d], 1);
            g_col[p] = s;
        }
    }
}

// ---------------- packed f32x2 helpers ---------------------------------------
__device__ __forceinline__ unsigned long long pack2(float x) {
    unsigned long long r;
    asm("mov.b64 %0, {%1, %1};" : "=l"(r) : "f"(x));
    return r;
}
__device__ __forceinline__ void fma2(unsigned long long& d,
                                     unsigned long long a,
                                     unsigned long long b) {
    asm("fma.rn.f32x2 %0, %1, %2, %0;" : "+l"(d) : "l"(a), "l"(b));
}
__device__ __forceinline__ float2 unpack2(unsigned long long v) {
    float lo, hi;
    asm("mov.b64 {%0, %1}, %2;" : "=f"(lo), "=f"(hi) : "l"(v));
    return make_float2(lo, hi);
}

// ---------------- GEMM body: H[n] = fp16( dinv[n] * (X[n] @ W) ) ------------
#define XS_STRIDE 68
__device__ __forceinline__ void gemm_body(const float* __restrict__ X,
                                          const float* __restrict__ W,
                                          __half* __restrict__ H, int N,
                                          int bid) {
    __shared__ float Ws[64 * 64];
    __shared__ float Xs[64 * XS_STRIDE];
    int tid  = threadIdx.x;
    int row0 = bid * 64;

    const float4* W4  = (const float4*)W;
    float4*       Ws4 = (float4*)Ws;
#pragma unroll
    for (int i = 0; i < 4; i++) Ws4[tid + 256 * i] = W4[tid + 256 * i];

    const float4* X4 = (const float4*)(X + (size_t)row0 * C);
#pragma unroll
    for (int i = 0; i < 4; i++) {
        int idx = tid + 256 * i;
        int r   = idx >> 4;
        int c4  = idx & 15;
        float4 v = make_float4(0.f, 0.f, 0.f, 0.f);
        if (row0 + r < N) v = X4[idx];
        *(float4*)(&Xs[r * XS_STRIDE + c4 * 4]) = v;
    }
    __syncthreads();

    int ty = tid >> 3;
    int tx = tid & 7;
    int r0 = ty, r1 = ty + 32;

    unsigned long long acc0[4] = {0, 0, 0, 0};
    unsigned long long acc1[4] = {0, 0, 0, 0};

#pragma unroll 8
    for (int k = 0; k < 64; k++) {
        unsigned long long xv0 = pack2(Xs[r0 * XS_STRIDE + k]);
        unsigned long long xv1 = pack2(Xs[r1 * XS_STRIDE + k]);
        const ulonglong2* wp = (const ulonglong2*)&Ws[k * 64 + tx * 8];
        ulonglong2 wa = wp[0];
        ulonglong2 wb = wp[1];
        fma2(acc0[0], xv0, wa.x); fma2(acc0[1], xv0, wa.y);
        fma2(acc0[2], xv0, wb.x); fma2(acc0[3], xv0, wb.y);
        fma2(acc1[0], xv1, wa.x); fma2(acc1[1], xv1, wa.y);
        fma2(acc1[2], xv1, wb.x); fma2(acc1[3], xv1, wb.y);
    }

    int g0 = row0 + r0, g1 = row0 + r1;
    if (g0 < N) {
        float dn = g_dinv[g0];
        float2 a = unpack2(acc0[0]), b = unpack2(acc0[1]);
        float2 c = unpack2(acc0[2]), d = unpack2(acc0[3]);
        __half2 h0 = __floats2half2_rn(dn * a.x, dn * a.y);
        __half2 h1 = __floats2half2_rn(dn * b.x, dn * b.y);
        __half2 h2 = __floats2half2_rn(dn * c.x, dn * c.y);
        __half2 h3 = __floats2half2_rn(dn * d.x, dn * d.y);
        uint4 pk = make_uint4(*(uint32_t*)&h0, *(uint32_t*)&h1,
                              *(uint32_t*)&h2, *(uint32_t*)&h3);
        *(uint4*)(H + (size_t)g0 * C + tx * 8) = pk;
    }
    if (g1 < N) {
        float dn = g_dinv[g1];
        float2 a = unpack2(acc1[0]), b = unpack2(acc1[1]);
        float2 c = unpack2(acc1[2]), d = unpack2(acc1[3]);
        __half2 h0 = __floats2half2_rn(dn * a.x, dn * a.y);
        __half2 h1 = __floats2half2_rn(dn * b.x, dn * b.y);
        __half2 h2 = __floats2half2_rn(dn * c.x, dn * c.y);
        __half2 h3 = __floats2half2_rn(dn * d.x, dn * d.y);
        uint4 pk = make_uint4(*(uint32_t*)&h0, *(uint32_t*)&h1,
                              *(uint32_t*)&h2, *(uint32_t*)&h3);
        *(uint4*)(H + (size_t)g1 * C + tx * 8) = pk;
    }
}

__global__ void __launch_bounds__(256) k_gemm(const float* __restrict__ X,
                                              const float* __restrict__ W,
                                              __half* __restrict__ H, int N) {
    gemm_body(X, W, H, N, blockIdx.x);
}

// Fused: blocks [0, SB) do scatter (CSR col fill), blocks [SB, SB+GB) do GEMM1.
// Both depend only on scan3 — they overlap inside one launch.
__global__ void __launch_bounds__(256) k_gemm_scatter(
        const float* __restrict__ X, const float* __restrict__ W,
        __half* __restrict__ H, int N,
        const void* __restrict__ eiv, int E, int SB) {
    if (blockIdx.x < SB) scatter_body(eiv, E, blockIdx.x);
    else                 gemm_body(X, W, H, N, blockIdx.x - SB);
}

// ---------------- aggregation on prescaled fp16 H ---------------------------
// out[n] = dinv[n] * (sum_{s in in(n)} H[s] + H[n]) + b
__global__ void __launch_bounds__(256) k_agg(const __half* __restrict__ H,
                                             const float* __restrict__ bias,
                                             float* __restrict__ out,
                                             int N, int relu) {
    int gid  = blockIdx.x * blockDim.x + threadIdx.x;
    int n    = gid >> 5;
    int lane = gid & 31;
    if (n >= N) return;
    int grp = lane >> 4;        // half-warp id
    int l16 = lane & 15;

    int beg = g_rowptr[n];
    int end = g_rowptr[n + 1];

    float4 acc = make_float4(0.f, 0.f, 0.f, 0.f);
    for (int p = beg; p < end; p += 32) {
        int remaining = end - p;
        int cnt = remaining < 32 ? remaining : 32;
        int sp = (lane < cnt) ? g_col[p + lane] : 0;
        int pairs = (cnt + 1) >> 1;
#pragma unroll 4
        for (int j = 0; j < pairs; j++) {
            int   idx = 2 * j + grp;
            int   s   = __shfl_sync(0xffffffffu, sp, idx);
            float m   = (idx < cnt) ? 1.f : 0.f;
            uint2 v   = ((const uint2*)(H + (size_t)s * C))[l16];
            float2 f0 = __half22float2(*(__half2*)&v.x);
            float2 f1 = __half22float2(*(__half2*)&v.y);
            acc.x += m * f0.x; acc.y += m * f0.y;
            acc.z += m * f1.x; acc.w += m * f1.y;
        }
    }
    acc.x += __shfl_xor_sync(0xffffffffu, acc.x, 16);
    acc.y += __shfl_xor_sync(0xffffffffu, acc.y, 16);
    acc.z += __shfl_xor_sync(0xffffffffu, acc.z, 16);
    acc.w += __shfl_xor_sync(0xffffffffu, acc.w, 16);

    if (lane < 16) {
        float dn  = g_dinv[n];
        uint2 v   = ((const uint2*)(H + (size_t)n * C))[l16];
        float2 f0 = __half22float2(*(__half2*)&v.x);
        float2 f1 = __half22float2(*(__half2*)&v.y);
        float4 bv = *(const float4*)(bias + l16 * 4);
        float4 r;
        r.x = dn * (acc.x + f0.x) + bv.x;
        r.y = dn * (acc.y + f0.y) + bv.y;
        r.z = dn * (acc.z + f1.x) + bv.z;
        r.w = dn * (acc.w + f1.y) + bv.w;
        if (relu) {
            r.x = fmaxf(r.x, 0.f); r.y = fmaxf(r.y, 0.f);
            r.z = fmaxf(r.z, 0.f); r.w = fmaxf(r.w, 0.f);
        }
        *(float4*)(out + (size_t)n * C + l16 * 4) = r;
    }
}

// ---------------- launch ----------------------------------------------------
extern "C" void kernel_launch(void* const* d_in, const int* in_sizes, int n_in,
                              void* d_out, int out_size) {
    const float* x   = (const float*)d_in[0];
    const void*  ei  = d_in[1];
    const float* W1  = (const float*)d_in[2];
    const float* b1  = (const float*)d_in[3];
    const float* W2  = (const float*)d_in[4];
    const float* b2  = (const float*)d_in[5];
    float*       out = (float*)d_out;

    int N = in_sizes[0] / C;     // 100000
    int E = in_sizes[1] / 2;     // 1200000

    __half* h1; cudaGetSymbolAddress((void**)&h1, g_h1);
    float*  h2; cudaGetSymbolAddress((void**)&h2, g_h2);

    int nb   = (N + SCAN_B - 1) / SCAN_B;   // 98
    int nblk = (N + 255) / 256;             // 391
    int SB   = (E + 255) / 256;             // scatter blocks
    int GB   = (N + 63) / 64;               // gemm blocks
    int AGB  = (N + 7) / 8;                 // agg blocks

    // preprocessing chain
    k_init<<<nblk, 256>>>((const int*)ei, E, N);
    k_hist<<<(E + 255) / 256, 256>>>(ei, E);
    k_scan1<<<nb, SCAN_B>>>(N);
    k_scan3<<<nblk + 1, 256>>>(N, nb);

    // layer 1: scatter (CSR fill) overlapped with GEMM1 in one launch
    k_gemm_scatter<<<SB + GB, 256>>>(x, W1, h1, N, ei, E, SB);
    k_agg<<<AGB, 256>>>(h1, b1, h2, N, 1);
    // layer 2
    k_gemm<<<GB, 256>>>(h2, W2, h1, N);
    k_agg<<<AGB, 256>>>(h1, b2, out, N, 0);
}

// round 6
// speedup vs baseline: 1.1337x; 1.0407x over previous
#include <cuda_runtime.h>
#include <cuda_fp16.h>
#include <stdint.h>

#define NN 100000
#define EMAX 1200000
#define C 64

// ---------------- scratch (device globals; no allocation allowed) ----------
__device__ __half g_ha[NN * C];    // 12.8 MB (gemm outputs, prescaled)
__device__ __half g_hb[NN * C];    // 12.8 MB (agg1 output = gemm2 input)
__device__ float  g_dinv[NN];
__device__ int    g_deg[NN];
__device__ int    g_partial[NN];
__device__ int    g_rowptr[NN + 1];
__device__ int    g_cursor[NN];
__device__ int    g_col[EMAX];
__device__ int    g_bsum[128];
__device__ int    g_is64;

// ---------------- init: zero degrees + dtype probe (fused) ------------------
__global__ void k_init(const int* __restrict__ ei, int E, int N) {
    int i = blockIdx.x * blockDim.x + threadIdx.x;
    if (i < N) g_deg[i] = 0;
    if (blockIdx.x == 0) {
        __shared__ int any_nonzero;
        if (threadIdx.x == 0) any_nonzero = 0;
        __syncthreads();
        int e = threadIdx.x * (E / 256);
        if (ei[2 * e + 1] != 0) any_nonzero = 1;
        __syncthreads();
        if (threadIdx.x == 0) g_is64 = (any_nonzero == 0);
    }
}

__device__ __forceinline__ int load_idx(const void* eiv, long long pos) {
    if (g_is64) return (int)((const long long*)eiv)[pos];
    return ((const int*)eiv)[pos];
}

// ---------------- preprocessing ---------------------------------------------
__global__ void k_hist(const void* __restrict__ eiv, int E) {
    int e = blockIdx.x * blockDim.x + threadIdx.x;
    if (e < E) {
        int d = load_idx(eiv, (long long)E + e);
        if ((unsigned)d < (unsigned)NN) atomicAdd(&g_deg[d], 1);
    }
}

#define SCAN_B 1024
__global__ void __launch_bounds__(SCAN_B) k_scan1(int N) {
    __shared__ int warpsum[32];
    int i    = blockIdx.x * SCAN_B + threadIdx.x;
    int lane = threadIdx.x & 31;
    int wid  = threadIdx.x >> 5;
    int v = (i < N) ? g_deg[i] : 0;
    int x = v;
#pragma unroll
    for (int o = 1; o < 32; o <<= 1) {
        int t = __shfl_up_sync(0xffffffffu, x, o);
        if (lane >= o) x += t;
    }
    if (lane == 31) warpsum[wid] = x;
    __syncthreads();
    if (wid == 0) {
        int s = warpsum[lane];
#pragma unroll
        for (int o = 1; o < 32; o <<= 1) {
            int t = __shfl_up_sync(0xffffffffu, s, o);
            if (lane >= o) s += t;
        }
        warpsum[lane] = s;
    }
    __syncthreads();
    int excl = x - v + (wid ? warpsum[wid - 1] : 0);
    if (i < N) g_partial[i] = excl;
    if (threadIdx.x == SCAN_B - 1) g_bsum[blockIdx.x] = excl + v;
}

__global__ void __launch_bounds__(256) k_scan3(int N, int nb) {
    __shared__ int sh[16];
    int t = threadIdx.x;
    int k = (blockIdx.x * 256) / SCAN_B;
    int vk = (t < k)  ? g_bsum[t] : 0;
    int va = (t < nb) ? g_bsum[t] : 0;
#pragma unroll
    for (int o = 16; o; o >>= 1) {
        vk += __shfl_xor_sync(0xffffffffu, vk, o);
        va += __shfl_xor_sync(0xffffffffu, va, o);
    }
    if ((t & 31) == 0) { sh[t >> 5] = vk; sh[8 + (t >> 5)] = va; }
    __syncthreads();
    if (t == 0) {
        int a = 0, b = 0;
#pragma unroll
        for (int w = 0; w < 8; w++) { a += sh[w]; b += sh[8 + w]; }
        sh[0] = a; sh[8] = b;
    }
    __syncthreads();
    int pre = sh[0], tot = sh[8];
    int i = blockIdx.x * 256 + t;
    if (i < N) {
        int r = g_partial[i] + pre;
        g_rowptr[i] = r;
        g_cursor[i] = r;
        g_dinv[i]   = rsqrtf((float)(g_deg[i] + 1));
    }
    if (i == N) g_rowptr[N] = tot;
}

__device__ __forceinline__ void scatter_body(const void* eiv, int E, int bid) {
    int e = bid * 256 + threadIdx.x;
    if (e < E) {
        int s = load_idx(eiv, e);
        int d = load_idx(eiv, (long long)E + e);
        if ((unsigned)s < (unsigned)NN && (unsigned)d < (unsigned)NN) {
            int p = atomicAdd(&g_cursor[d], 1);
            g_col[p] = s;
        }
    }
}

// ---------------- packed f32x2 helpers ---------------------------------------
__device__ __forceinline__ unsigned long long pack2(float x) {
    unsigned long long r;
    asm("mov.b64 %0, {%1, %1};" : "=l"(r) : "f"(x));
    return r;
}
__device__ __forceinline__ void fma2(unsigned long long& d,
                                     unsigned long long a,
                                     unsigned long long b) {
    asm("fma.rn.f32x2 %0, %1, %2, %0;" : "+l"(d) : "l"(a), "l"(b));
}
__device__ __forceinline__ float2 unpack2(unsigned long long v) {
    float lo, hi;
    asm("mov.b64 {%0, %1}, %2;" : "=f"(lo), "=f"(hi) : "l"(v));
    return make_float2(lo, hi);
}

// ---------------- X-tile loaders (fp32 / fp16 inputs) ------------------------
#define XS_STRIDE 68
__device__ __forceinline__ void load_x_tile(const float* __restrict__ X,
                                            float* Xs, int row0, int N, int tid) {
    const float4* X4 = (const float4*)(X + (size_t)row0 * C);
#pragma unroll
    for (int i = 0; i < 4; i++) {
        int idx = tid + 256 * i;
        int r   = idx >> 4;
        int c4  = idx & 15;
        float4 v = make_float4(0.f, 0.f, 0.f, 0.f);
        if (row0 + r < N) v = X4[idx];
        *(float4*)(&Xs[r * XS_STRIDE + c4 * 4]) = v;
    }
}
__device__ __forceinline__ void load_x_tile(const __half* __restrict__ X,
                                            float* Xs, int row0, int N, int tid) {
    const uint4* X8 = (const uint4*)(X + (size_t)row0 * C);  // 8 halves each
#pragma unroll
    for (int i = 0; i < 2; i++) {
        int idx = tid + 256 * i;      // 512 uint4 total
        int r   = idx >> 3;
        int c8  = idx & 7;
        uint4 v = make_uint4(0, 0, 0, 0);
        if (row0 + r < N) v = X8[idx];
        float* d = &Xs[r * XS_STRIDE + c8 * 8];
        float2 f;
        f = __half22float2(*(__half2*)&v.x); d[0] = f.x; d[1] = f.y;
        f = __half22float2(*(__half2*)&v.y); d[2] = f.x; d[3] = f.y;
        f = __half22float2(*(__half2*)&v.z); d[4] = f.x; d[5] = f.y;
        f = __half22float2(*(__half2*)&v.w); d[6] = f.x; d[7] = f.y;
    }
}

// ---------------- GEMM body: H[n] = fp16( dinv[n] * (X[n] @ W) ) ------------
template <typename T>
__device__ __forceinline__ void gemm_body(const T* __restrict__ X,
                                          const float* __restrict__ W,
                                          __half* __restrict__ H, int N,
                                          int bid) {
    __shared__ float Ws[64 * 64];
    __shared__ float Xs[64 * XS_STRIDE];
    int tid  = threadIdx.x;
    int row0 = bid * 64;

    const float4* W4  = (const float4*)W;
    float4*       Ws4 = (float4*)Ws;
#pragma unroll
    for (int i = 0; i < 4; i++) Ws4[tid + 256 * i] = W4[tid + 256 * i];

    load_x_tile(X, Xs, row0, N, tid);
    __syncthreads();

    int ty = tid >> 3;
    int tx = tid & 7;
    int r0 = ty, r1 = ty + 32;

    unsigned long long acc0[4] = {0, 0, 0, 0};
    unsigned long long acc1[4] = {0, 0, 0, 0};

#pragma unroll 8
    for (int k = 0; k < 64; k++) {
        unsigned long long xv0 = pack2(Xs[r0 * XS_STRIDE + k]);
        unsigned long long xv1 = pack2(Xs[r1 * XS_STRIDE + k]);
        const ulonglong2* wp = (const ulonglong2*)&Ws[k * 64 + tx * 8];
        ulonglong2 wa = wp[0];
        ulonglong2 wb = wp[1];
        fma2(acc0[0], xv0, wa.x); fma2(acc0[1], xv0, wa.y);
        fma2(acc0[2], xv0, wb.x); fma2(acc0[3], xv0, wb.y);
        fma2(acc1[0], xv1, wa.x); fma2(acc1[1], xv1, wa.y);
        fma2(acc1[2], xv1, wb.x); fma2(acc1[3], xv1, wb.y);
    }

    int g0 = row0 + r0, g1 = row0 + r1;
    if (g0 < N) {
        float dn = g_dinv[g0];
        float2 a = unpack2(acc0[0]), b = unpack2(acc0[1]);
        float2 c = unpack2(acc0[2]), d = unpack2(acc0[3]);
        __half2 h0 = __floats2half2_rn(dn * a.x, dn * a.y);
        __half2 h1 = __floats2half2_rn(dn * b.x, dn * b.y);
        __half2 h2 = __floats2half2_rn(dn * c.x, dn * c.y);
        __half2 h3 = __floats2half2_rn(dn * d.x, dn * d.y);
        uint4 pk = make_uint4(*(uint32_t*)&h0, *(uint32_t*)&h1,
                              *(uint32_t*)&h2, *(uint32_t*)&h3);
        *(uint4*)(H + (size_t)g0 * C + tx * 8) = pk;
    }
    if (g1 < N) {
        float dn = g_dinv[g1];
        float2 a = unpack2(acc1[0]), b = unpack2(acc1[1]);
        float2 c = unpack2(acc1[2]), d = unpack2(acc1[3]);
        __half2 h0 = __floats2half2_rn(dn * a.x, dn * a.y);
        __half2 h1 = __floats2half2_rn(dn * b.x, dn * b.y);
        __half2 h2 = __floats2half2_rn(dn * c.x, dn * c.y);
        __half2 h3 = __floats2half2_rn(dn * d.x, dn * d.y);
        uint4 pk = make_uint4(*(uint32_t*)&h0, *(uint32_t*)&h1,
                              *(uint32_t*)&h2, *(uint32_t*)&h3);
        *(uint4*)(H + (size_t)g1 * C + tx * 8) = pk;
    }
}

__global__ void __launch_bounds__(256) k_gemm_h(const __half* __restrict__ X,
                                                const float* __restrict__ W,
                                                __half* __restrict__ H, int N) {
    gemm_body<__half>(X, W, H, N, blockIdx.x);
}

// Fused: blocks [0, SB) scatter (CSR fill), blocks [SB, ...) do GEMM1 (fp32 X).
__global__ void __launch_bounds__(256) k_gemm_scatter(
        const float* __restrict__ X, const float* __restrict__ W,
        __half* __restrict__ H, int N,
        const void* __restrict__ eiv, int E, int SB) {
    if (blockIdx.x < SB) scatter_body(eiv, E, blockIdx.x);
    else                 gemm_body<float>(X, W, H, N, blockIdx.x - SB);
}

// ---------------- aggregation: 2 nodes per warp (16-lane groups) ------------
// out[n] = dinv[n] * (sum_{s in in(n)} H[s] + H[n]) + b ; H is prescaled fp16.
// Each 16-lane group owns one node's full 128B row (8B per lane) -> no final
// cross-lane reduction needed.
template <bool HALF_OUT, bool RELU>
__global__ void __launch_bounds__(256) k_agg(const __half* __restrict__ H,
                                             const float* __restrict__ bias,
                                             void* __restrict__ outv, int N) {
    const unsigned F = 0xffffffffu;
    int gid  = blockIdx.x * blockDim.x + threadIdx.x;
    int warp = gid >> 5;
    int lane = gid & 31;
    int g    = lane >> 4;
    int l16  = lane & 15;
    int n    = warp * 2 + g;
    bool act = (n < N);

    int beg = 0, end = 0;
    if (act) { beg = g_rowptr[n]; end = g_rowptr[n + 1]; }
    int len    = end - beg;
    int lenmax = max(len, __shfl_xor_sync(F, len, 16));

    float4 acc = make_float4(0.f, 0.f, 0.f, 0.f);
    for (int off = 0; off < lenmax; off += 16) {
        int cnt = min(len - off, 16);                 // may be <= 0
        int sp  = (l16 < cnt) ? g_col[beg + off + l16] : 0;
        int cm  = max(cnt, __shfl_xor_sync(F, cnt, 16));
#pragma unroll 4
        for (int j = 0; j < cm; j++) {
            int   s = __shfl_sync(F, sp, (g << 4) + j);
            float m = (j < cnt) ? 1.f : 0.f;
            uint2 v = ((const uint2*)(H + (size_t)s * C))[l16];
            float2 a0 = __half22float2(*(__half2*)&v.x);
            float2 a1 = __half22float2(*(__half2*)&v.y);
            acc.x += m * a0.x; acc.y += m * a0.y;
            acc.z += m * a1.x; acc.w += m * a1.y;
        }
    }

    if (act) {
        float dn = g_dinv[n];
        uint2 hv = ((const uint2*)(H + (size_t)n * C))[l16];
        float2 f0 = __half22float2(*(__half2*)&hv.x);
        float2 f1 = __half22float2(*(__half2*)&hv.y);
        float4 bv = *(const float4*)(bias + l16 * 4);
        float4 r;
        r.x = dn * (acc.x + f0.x) + bv.x;
        r.y = dn * (acc.y + f0.y) + bv.y;
        r.z = dn * (acc.z + f1.x) + bv.z;
        r.w = dn * (acc.w + f1.y) + bv.w;
        if (RELU) {
            r.x = fmaxf(r.x, 0.f); r.y = fmaxf(r.y, 0.f);
            r.z = fmaxf(r.z, 0.f); r.w = fmaxf(r.w, 0.f);
        }
        if (HALF_OUT) {
            __half2 o0 = __floats2half2_rn(r.x, r.y);
            __half2 o1 = __floats2half2_rn(r.z, r.w);
            uint2 pk = make_uint2(*(uint32_t*)&o0, *(uint32_t*)&o1);
            ((uint2*)((__half*)outv + (size_t)n * C))[l16] = pk;
        } else {
            ((float4*)((float*)outv + (size_t)n * C))[l16] = r;
        }
    }
}

// ---------------- launch ----------------------------------------------------
extern "C" void kernel_launch(void* const* d_in, const int* in_sizes, int n_in,
                              void* d_out, int out_size) {
    const float* x   = (const float*)d_in[0];
    const void*  ei  = d_in[1];
    const float* W1  = (const float*)d_in[2];
    const float* b1  = (const float*)d_in[3];
    const float* W2  = (const float*)d_in[4];
    const float* b2  = (const float*)d_in[5];
    float*       out = (float*)d_out;

    int N = in_sizes[0] / C;     // 100000
    int E = in_sizes[1] / 2;     // 1200000

    __half* ha; cudaGetSymbolAddress((void**)&ha, g_ha);
    __half* hb; cudaGetSymbolAddress((void**)&hb, g_hb);

    int nb   = (N + SCAN_B - 1) / SCAN_B;   // 98
    int nblk = (N + 255) / 256;             // 391
    int SB   = (E + 255) / 256;             // scatter blocks
    int GB   = (N + 63) / 64;               // gemm blocks
    int AGB  = (N + 15) / 16;               // agg blocks (16 nodes per block)

    // preprocessing chain
    k_init<<<nblk, 256>>>((const int*)ei, E, N);
    k_hist<<<(E + 255) / 256, 256>>>(ei, E);
    k_scan1<<<nb, SCAN_B>>>(N);
    k_scan3<<<nblk + 1, 256>>>(N, nb);

    // layer 1: scatter overlapped with GEMM1 in one launch
    k_gemm_scatter<<<SB + GB, 256>>>(x, W1, ha, N, ei, E, SB);
    k_agg<true, true><<<AGB, 256>>>(ha, b1, hb, N);
    // layer 2
    k_gemm_h<<<GB, 256>>>(hb, W2, ha, N);
    k_agg<false, false><<<AGB, 256>>>(ha, b2, out, N);
}

// round 7
// speedup vs baseline: 1.1354x; 1.0014x over previous
#include <cuda_runtime.h>
#include <cuda_fp16.h>
#include <stdint.h>

#define NN 100000
#define EMAX 1200000
#define C 64
#define NB_PRE 444   // 3 blocks/SM on 148 SMs -> co-residency guaranteed

// ---------------- scratch (device globals; no allocation allowed) ----------
__device__ __half g_ha[NN * C];
__device__ __half g_hb[NN * C];
__device__ float  g_dinv[NN];
__device__ int    g_deg[NN];
__device__ int    g_partial[NN];
__device__ int    g_rowptr[NN + 1];
__device__ int    g_cursor[NN];
__device__ int    g_col[EMAX];
__device__ int    g_bsum[640];
__device__ int    g_is64;
__device__ int    g_barA[8];
__device__ int    g_barD[8];

// ---------------- device-wide barrier (self-resetting, replay-safe) ---------
__device__ __forceinline__ void grid_barrier(int slot, int nb) {
    __syncthreads();
    if (threadIdx.x == 0) {
        __threadfence();
        atomicAdd(&g_barA[slot], 1);
        while (atomicAdd(&g_barA[slot], 0) < nb) __nanosleep(64);
        __threadfence();
        int d = atomicAdd(&g_barD[slot], 1);
        if (d == nb - 1) {           // last departer resets for next replay
            atomicExch(&g_barA[slot], 0);
            atomicExch(&g_barD[slot], 0);
        }
    }
    __syncthreads();
}

// 256-thread block exclusive scan; also returns block total.
__device__ __forceinline__ int blk_excl_scan256(int v, int* tot) {
    __shared__ int ws[8];
    int lane = threadIdx.x & 31, w = threadIdx.x >> 5;
    int x = v;
#pragma unroll
    for (int o = 1; o < 32; o <<= 1) {
        int u = __shfl_up_sync(0xffffffffu, x, o);
        if (lane >= o) x += u;
    }
    if (lane == 31) ws[w] = x;
    __syncthreads();
    if (w == 0) {
        int s = (lane < 8) ? ws[lane] : 0;
#pragma unroll
        for (int o = 1; o < 8; o <<= 1) {
            int u = __shfl_up_sync(0xffffffffu, s, o);
            if (lane >= o) s += u;
        }
        if (lane < 8) ws[lane] = s;
    }
    __syncthreads();
    *tot = ws[7];
    int excl = x - v + (w ? ws[w - 1] : 0);
    __syncthreads();   // ws reusable by next call
    return excl;
}

__device__ __forceinline__ int load_idx(const void* eiv, long long pos) {
    if (g_is64) return (int)((const long long*)eiv)[pos];
    return ((const int*)eiv)[pos];
}

// ---------------- fused persistent preprocessing ----------------------------
// P0 zero deg + dtype probe | P1 degree hist | P2 per-block scan |
// P3 block-offset scan | P4 rowptr/cursor/dinv
__global__ void __launch_bounds__(256, 4) k_pre(const void* __restrict__ eiv,
                                                int E, int N, int CH) {
    int b = blockIdx.x, t = threadIdx.x;
    const int NB = gridDim.x;

    // P0
    for (int i = b * 256 + t; i < N; i += NB * 256) g_deg[i] = 0;
    if (b == 0) {
        __shared__ int anz;
        if (t == 0) anz = 0;
        __syncthreads();
        int e = t * (E / 256);
        if (((const int*)eiv)[2 * e + 1] != 0) anz = 1;
        __syncthreads();
        if (t == 0) g_is64 = (anz == 0);
    }
    grid_barrier(0, NB);

    // P1: histogram of dst degrees
    for (int e = b * 256 + t; e < E; e += NB * 256) {
        int d = load_idx(eiv, (long long)E + e);
        if ((unsigned)d < (unsigned)NN) atomicAdd(&g_deg[d], 1);
    }
    grid_barrier(1, NB);

    // P2: block-local exclusive scan over this block's chunk
    {
        int i = b * CH + t;
        int v = (t < CH && i < N) ? g_deg[i] : 0;
        int tot;
        int ex = blk_excl_scan256(v, &tot);
        if (t < CH && i < N) g_partial[i] = ex;
        if (t == 0) g_bsum[b] = tot;
    }
    grid_barrier(2, NB);

    // P3: block 0 turns bsums into exclusive offsets (2 per thread covers 512)
    if (b == 0) {
        int i0 = t * 2;
        int a0 = (i0     < NB) ? g_bsum[i0]     : 0;
        int a1 = (i0 + 1 < NB) ? g_bsum[i0 + 1] : 0;
        int tot;
        int ex = blk_excl_scan256(a0 + a1, &tot);
        if (i0     < NB) g_bsum[i0]     = ex;
        if (i0 + 1 < NB) g_bsum[i0 + 1] = ex + a0;
        if (t == 0) g_rowptr[N] = tot;
    }
    grid_barrier(3, NB);

    // P4: final rowptr / cursor / dinv
    {
        int i = b * CH + t;
        if (t < CH && i < N) {
            int r = g_partial[i] + g_bsum[b];
            g_rowptr[i] = r;
            g_cursor[i] = r;
            g_dinv[i]   = rsqrtf((float)(g_deg[i] + 1));
        }
    }
}

__device__ __forceinline__ void scatter_body(const void* eiv, int E, int bid) {
    int e = bid * 256 + threadIdx.x;
    if (e < E) {
        int s = load_idx(eiv, e);
        int d = load_idx(eiv, (long long)E + e);
        if ((unsigned)s < (unsigned)NN && (unsigned)d < (unsigned)NN) {
            int p = atomicAdd(&g_cursor[d], 1);
            g_col[p] = s;
        }
    }
}

// ---------------- packed f32x2 helpers ---------------------------------------
__device__ __forceinline__ unsigned long long pack2(float x) {
    unsigned long long r;
    asm("mov.b64 %0, {%1, %1};" : "=l"(r) : "f"(x));
    return r;
}
__device__ __forceinline__ void fma2(unsigned long long& d,
                                     unsigned long long a,
                                     unsigned long long b) {
    asm("fma.rn.f32x2 %0, %1, %2, %0;" : "+l"(d) : "l"(a), "l"(b));
}
__device__ __forceinline__ float2 unpack2(unsigned long long v) {
    float lo, hi;
    asm("mov.b64 {%0, %1}, %2;" : "=f"(lo), "=f"(hi) : "l"(v));
    return make_float2(lo, hi);
}

// ---------------- X-tile loaders ---------------------------------------------
#define XS_STRIDE 68
__device__ __forceinline__ void load_x_tile(const float* __restrict__ X,
                                            float* Xs, int row0, int N, int tid) {
    const float4* X4 = (const float4*)(X + (size_t)row0 * C);
#pragma unroll
    for (int i = 0; i < 4; i++) {
        int idx = tid + 256 * i;
        int r   = idx >> 4;
        int c4  = idx & 15;
        float4 v = make_float4(0.f, 0.f, 0.f, 0.f);
        if (row0 + r < N) v = X4[idx];
        *(float4*)(&Xs[r * XS_STRIDE + c4 * 4]) = v;
    }
}
__device__ __forceinline__ void load_x_tile(const __half* __restrict__ X,
                                            float* Xs, int row0, int N, int tid) {
    const uint4* X8 = (const uint4*)(X + (size_t)row0 * C);
#pragma unroll
    for (int i = 0; i < 2; i++) {
        int idx = tid + 256 * i;
        int r   = idx >> 3;
        int c8  = idx & 7;
        uint4 v = make_uint4(0, 0, 0, 0);
        if (row0 + r < N) v = X8[idx];
        float* d = &Xs[r * XS_STRIDE + c8 * 8];
        float2 f;
        f = __half22float2(*(__half2*)&v.x); d[0] = f.x; d[1] = f.y;
        f = __half22float2(*(__half2*)&v.y); d[2] = f.x; d[3] = f.y;
        f = __half22float2(*(__half2*)&v.z); d[4] = f.x; d[5] = f.y;
        f = __half22float2(*(__half2*)&v.w); d[6] = f.x; d[7] = f.y;
    }
}

// ---------------- GEMM body: H[n] = fp16( dinv[n] * (X[n] @ W) ) ------------
template <typename T>
__device__ __forceinline__ void gemm_body(const T* __restrict__ X,
                                          const float* __restrict__ W,
                                          __half* __restrict__ H, int N,
                                          int bid) {
    __shared__ float Ws[64 * 64];
    __shared__ float Xs[64 * XS_STRIDE];
    int tid  = threadIdx.x;
    int row0 = bid * 64;

    const float4* W4  = (const float4*)W;
    float4*       Ws4 = (float4*)Ws;
#pragma unroll
    for (int i = 0; i < 4; i++) Ws4[tid + 256 * i] = W4[tid + 256 * i];

    load_x_tile(X, Xs, row0, N, tid);
    __syncthreads();

    int ty = tid >> 3;
    int tx = tid & 7;
    int r0 = ty, r1 = ty + 32;

    unsigned long long acc0[4] = {0, 0, 0, 0};
    unsigned long long acc1[4] = {0, 0, 0, 0};

#pragma unroll 8
    for (int k = 0; k < 64; k++) {
        unsigned long long xv0 = pack2(Xs[r0 * XS_STRIDE + k]);
        unsigned long long xv1 = pack2(Xs[r1 * XS_STRIDE + k]);
        const ulonglong2* wp = (const ulonglong2*)&Ws[k * 64 + tx * 8];
        ulonglong2 wa = wp[0];
        ulonglong2 wb = wp[1];
        fma2(acc0[0], xv0, wa.x); fma2(acc0[1], xv0, wa.y);
        fma2(acc0[2], xv0, wb.x); fma2(acc0[3], xv0, wb.y);
        fma2(acc1[0], xv1, wa.x); fma2(acc1[1], xv1, wa.y);
        fma2(acc1[2], xv1, wb.x); fma2(acc1[3], xv1, wb.y);
    }

    int g0 = row0 + r0, g1 = row0 + r1;
    if (g0 < N) {
        float dn = g_dinv[g0];
        float2 a = unpack2(acc0[0]), b = unpack2(acc0[1]);
        float2 c = unpack2(acc0[2]), d = unpack2(acc0[3]);
        __half2 h0 = __floats2half2_rn(dn * a.x, dn * a.y);
        __half2 h1 = __floats2half2_rn(dn * b.x, dn * b.y);
        __half2 h2 = __floats2half2_rn(dn * c.x, dn * c.y);
        __half2 h3 = __floats2half2_rn(dn * d.x, dn * d.y);
        uint4 pk = make_uint4(*(uint32_t*)&h0, *(uint32_t*)&h1,
                              *(uint32_t*)&h2, *(uint32_t*)&h3);
        *(uint4*)(H + (size_t)g0 * C + tx * 8) = pk;
    }
    if (g1 < N) {
        float dn = g_dinv[g1];
        float2 a = unpack2(acc1[0]), b = unpack2(acc1[1]);
        float2 c = unpack2(acc1[2]), d = unpack2(acc1[3]);
        __half2 h0 = __floats2half2_rn(dn * a.x, dn * a.y);
        __half2 h1 = __floats2half2_rn(dn * b.x, dn * b.y);
        __half2 h2 = __floats2half2_rn(dn * c.x, dn * c.y);
        __half2 h3 = __floats2half2_rn(dn * d.x, dn * d.y);
        uint4 pk = make_uint4(*(uint32_t*)&h0, *(uint32_t*)&h1,
                              *(uint32_t*)&h2, *(uint32_t*)&h3);
        *(uint4*)(H + (size_t)g1 * C + tx * 8) = pk;
    }
}

__global__ void __launch_bounds__(256) k_gemm_h(const __half* __restrict__ X,
                                                const float* __restrict__ W,
                                                __half* __restrict__ H, int N) {
    gemm_body<__half>(X, W, H, N, blockIdx.x);
}

__global__ void __launch_bounds__(256) k_gemm_scatter(
        const float* __restrict__ X, const float* __restrict__ W,
        __half* __restrict__ H, int N,
        const void* __restrict__ eiv, int E, int SB) {
    if (blockIdx.x < SB) scatter_body(eiv, E, blockIdx.x);
    else                 gemm_body<float>(X, W, H, N, blockIdx.x - SB);
}

// ---------------- aggregation: 4 nodes per warp (8-lane groups) -------------
// out[n] = dinv[n] * (sum_{s in in(n)} H[s] + H[n]) + b ; H prescaled fp16.
// Each 8-lane group owns one node's 128B row via one LDG.128 per lane.
template <bool HALF_OUT, bool RELU>
__global__ void __launch_bounds__(256) k_agg(const __half* __restrict__ H,
                                             const float* __restrict__ bias,
                                             void* __restrict__ outv, int N) {
    const unsigned F = 0xffffffffu;
    int gid  = blockIdx.x * blockDim.x + threadIdx.x;
    int warp = gid >> 5;
    int lane = gid & 31;
    int g    = lane >> 3;
    int l8   = lane & 7;
    int n    = warp * 4 + g;
    bool act = (n < N);

    int beg = 0, end = 0;
    if (act) { beg = g_rowptr[n]; end = g_rowptr[n + 1]; }
    int len = end - beg;
    int lm  = len;
    lm = max(lm, __shfl_xor_sync(F, lm, 8));
    lm = max(lm, __shfl_xor_sync(F, lm, 16));

    float a0=0.f,a1=0.f,a2=0.f,a3=0.f,a4=0.f,a5=0.f,a6=0.f,a7=0.f;
    for (int off = 0; off < lm; off += 8) {
        int cnt = min(len - off, 8);                 // may be <= 0
        int sp  = (l8 < cnt) ? g_col[beg + off + l8] : 0;
        int cm  = cnt;
        cm = max(cm, __shfl_xor_sync(F, cm, 8));
        cm = max(cm, __shfl_xor_sync(F, cm, 16));
#pragma unroll 4
        for (int j = 0; j < cm; j++) {
            int   s = __shfl_sync(F, sp, (g << 3) + j);
            float m = (j < cnt) ? 1.f : 0.f;
            uint4 v = *(const uint4*)(H + (size_t)s * C + l8 * 8);
            float2 f0 = __half22float2(*(__half2*)&v.x);
            float2 f1 = __half22float2(*(__half2*)&v.y);
            float2 f2 = __half22float2(*(__half2*)&v.z);
            float2 f3 = __half22float2(*(__half2*)&v.w);
            a0 += m * f0.x; a1 += m * f0.y; a2 += m * f1.x; a3 += m * f1.y;
            a4 += m * f2.x; a5 += m * f2.y; a6 += m * f3.x; a7 += m * f3.y;
        }
    }

    if (act) {
        float dn = g_dinv[n];
        uint4 hv = *(const uint4*)(H + (size_t)n * C + l8 * 8);
        float2 h0 = __half22float2(*(__half2*)&hv.x);
        float2 h1 = __half22float2(*(__half2*)&hv.y);
        float2 h2 = __half22float2(*(__half2*)&hv.z);
        float2 h3 = __half22float2(*(__half2*)&hv.w);
        float4 bA = *(const float4*)(bias + l8 * 8);
        float4 bB = *(const float4*)(bias + l8 * 8 + 4);
        float r0 = dn * (a0 + h0.x) + bA.x;
        float r1 = dn * (a1 + h0.y) + bA.y;
        float r2 = dn * (a2 + h1.x) + bA.z;
        float r3 = dn * (a3 + h1.y) + bA.w;
        float r4 = dn * (a4 + h2.x) + bB.x;
        float r5 = dn * (a5 + h2.y) + bB.y;
        float r6 = dn * (a6 + h3.x) + bB.z;
        float r7 = dn * (a7 + h3.y) + bB.w;
        if (RELU) {
            r0 = fmaxf(r0, 0.f); r1 = fmaxf(r1, 0.f);
            r2 = fmaxf(r2, 0.f); r3 = fmaxf(r3, 0.f);
            r4 = fmaxf(r4, 0.f); r5 = fmaxf(r5, 0.f);
            r6 = fmaxf(r6, 0.f); r7 = fmaxf(r7, 0.f);
        }
        if (HALF_OUT) {
            __half2 o0 = __floats2half2_rn(r0, r1);
            __half2 o1 = __floats2half2_rn(r2, r3);
            __half2 o2 = __floats2half2_rn(r4, r5);
            __half2 o3 = __floats2half2_rn(r6, r7);
            uint4 pk = make_uint4(*(uint32_t*)&o0, *(uint32_t*)&o1,
                                  *(uint32_t*)&o2, *(uint32_t*)&o3);
            *(uint4*)((__half*)outv + (size_t)n * C + l8 * 8) = pk;
        } else {
            float* o = (float*)outv + (size_t)n * C + l8 * 8;
            *(float4*)o       = make_float4(r0, r1, r2, r3);
            *(float4*)(o + 4) = make_float4(r4, r5, r6, r7);
        }
    }
}

// ---------------- launch ----------------------------------------------------
extern "C" void kernel_launch(void* const* d_in, const int* in_sizes, int n_in,
                              void* d_out, int out_size) {
    const float* x   = (const float*)d_in[0];
    const void*  ei  = d_in[1];
    const float* W1  = (const float*)d_in[2];
    const float* b1  = (const float*)d_in[3];
    const float* W2  = (const float*)d_in[4];
    const float* b2  = (const float*)d_in[5];
    float*       out = (float*)d_out;

    int N = in_sizes[0] / C;     // 100000
    int E = in_sizes[1] / 2;     // 1200000

    __half* ha; cudaGetSymbolAddress((void**)&ha, g_ha);
    __half* hb; cudaGetSymbolAddress((void**)&hb, g_hb);

    int CH  = (N + NB_PRE - 1) / NB_PRE;    // 226 <= 256
    int SB  = (E + 255) / 256;              // scatter blocks
    int GB  = (N + 63) / 64;                // gemm blocks
    int AGB = (N + 31) / 32;                // agg blocks (32 nodes per block)

    // 1 fused preprocessing launch (deg/dinv/rowptr/cursor)
    k_pre<<<NB_PRE, 256>>>(ei, E, N, CH);

    // layer 1: CSR scatter overlapped with GEMM1 in one launch
    k_gemm_scatter<<<SB + GB, 256>>>(x, W1, ha, N, ei, E, SB);
    k_agg<true, true><<<AGB, 256>>>(ha, b1, hb, N);
    // layer 2
    k_gemm_h<<<GB, 256>>>(hb, W2, ha, N);
    k_agg<false, false><<<AGB, 256>>>(ha, b2, out, N);
}

// round 8
// speedup vs baseline: 2.1849x; 1.9244x over previous
#include <cuda_runtime.h>
#include <cuda_fp16.h>
#include <stdint.h>

#define NN 100000
#define EMAX 1200000
#define C 64
#define NB_PRE 444   // 3 blocks/SM on 148 SMs -> co-residency guaranteed

// ---------------- scratch (device globals; no allocation allowed) ----------
__device__ __half g_ha[NN * C];
__device__ __half g_hb[NN * C];
__device__ float  g_dinv[NN];
__device__ int    g_deg[NN];
__device__ int    g_partial[NN];
__device__ int    g_rowptr[NN + 1];
__device__ int    g_cursor[NN];
__device__ int    g_col[EMAX];
__device__ int    g_bsum[640];
__device__ int    g_is64;
__device__ int    g_barA[8];
__device__ int    g_barD[8];

// ---------------- device-wide barrier (self-resetting, replay-safe) ---------
__device__ __forceinline__ void grid_barrier(int slot, int nb) {
    __syncthreads();
    if (threadIdx.x == 0) {
        __threadfence();
        atomicAdd(&g_barA[slot], 1);
        while (atomicAdd(&g_barA[slot], 0) < nb) __nanosleep(64);
        __threadfence();
        int d = atomicAdd(&g_barD[slot], 1);
        if (d == nb - 1) {
            atomicExch(&g_barA[slot], 0);
            atomicExch(&g_barD[slot], 0);
        }
    }
    __syncthreads();
}

__device__ __forceinline__ int blk_excl_scan256(int v, int* tot) {
    __shared__ int ws[8];
    int lane = threadIdx.x & 31, w = threadIdx.x >> 5;
    int x = v;
#pragma unroll
    for (int o = 1; o < 32; o <<= 1) {
        int u = __shfl_up_sync(0xffffffffu, x, o);
        if (lane >= o) x += u;
    }
    if (lane == 31) ws[w] = x;
    __syncthreads();
    if (w == 0) {
        int s = (lane < 8) ? ws[lane] : 0;
#pragma unroll
        for (int o = 1; o < 8; o <<= 1) {
            int u = __shfl_up_sync(0xffffffffu, s, o);
            if (lane >= o) s += u;
        }
        if (lane < 8) ws[lane] = s;
    }
    __syncthreads();
    *tot = ws[7];
    int excl = x - v + (w ? ws[w - 1] : 0);
    __syncthreads();
    return excl;
}

__device__ __forceinline__ int load_idx(const void* eiv, long long pos) {
    if (g_is64) return (int)((const long long*)eiv)[pos];
    return ((const int*)eiv)[pos];
}

// ---------------- fused persistent preprocessing ----------------------------
__global__ void __launch_bounds__(256, 4) k_pre(const void* __restrict__ eiv,
                                                int E, int N, int CH) {
    int b = blockIdx.x, t = threadIdx.x;
    const int NB = gridDim.x;

    for (int i = b * 256 + t; i < N; i += NB * 256) g_deg[i] = 0;
    if (b == 0) {
        __shared__ int anz;
        if (t == 0) anz = 0;
        __syncthreads();
        int e = t * (E / 256);
        if (((const int*)eiv)[2 * e + 1] != 0) anz = 1;
        __syncthreads();
        if (t == 0) g_is64 = (anz == 0);
    }
    grid_barrier(0, NB);

    for (int e = b * 256 + t; e < E; e += NB * 256) {
        int d = load_idx(eiv, (long long)E + e);
        if ((unsigned)d < (unsigned)NN) atomicAdd(&g_deg[d], 1);
    }
    grid_barrier(1, NB);

    {
        int i = b * CH + t;
        int v = (t < CH && i < N) ? g_deg[i] : 0;
        int tot;
        int ex = blk_excl_scan256(v, &tot);
        if (t < CH && i < N) g_partial[i] = ex;
        if (t == 0) g_bsum[b] = tot;
    }
    grid_barrier(2, NB);

    if (b == 0) {
        int i0 = t * 2;
        int a0 = (i0     < NB) ? g_bsum[i0]     : 0;
        int a1 = (i0 + 1 < NB) ? g_bsum[i0 + 1] : 0;
        int tot;
        int ex = blk_excl_scan256(a0 + a1, &tot);
        if (i0     < NB) g_bsum[i0]     = ex;
        if (i0 + 1 < NB) g_bsum[i0 + 1] = ex + a0;
        if (t == 0) g_rowptr[N] = tot;
    }
    grid_barrier(3, NB);

    {
        int i = b * CH + t;
        if (t < CH && i < N) {
            int r = g_partial[i] + g_bsum[b];
            g_rowptr[i] = r;
            g_cursor[i] = r;
            g_dinv[i]   = rsqrtf((float)(g_deg[i] + 1));
        }
    }
}

__device__ __forceinline__ void scatter_body(const void* eiv, int E, int bid) {
    int e = bid * 256 + threadIdx.x;
    if (e < E) {
        int s = load_idx(eiv, e);
        int d = load_idx(eiv, (long long)E + e);
        if ((unsigned)s < (unsigned)NN && (unsigned)d < (unsigned)NN) {
            int p = atomicAdd(&g_cursor[d], 1);
            g_col[p] = s;
        }
    }
}

// ---------------- tensor-core GEMM (mma.sync HMMA) ---------------------------
// H[n] = fp16( dinv[n] * (X[n] @ W) ),  X: [N,64], W: [64,64].
// Block = 256 thr = 8 warps, tile = 128 rows x 64 cols. fp16 operands in smem
// with 72-half row stride (16B chunks rotate banks -> LDSM conflict-free).
#define AS_STR 72

__device__ __forceinline__ void ldsm4(uint32_t& r0, uint32_t& r1,
                                      uint32_t& r2, uint32_t& r3, uint32_t a) {
    asm volatile("ldmatrix.sync.aligned.m8n8.x4.shared.b16 {%0,%1,%2,%3}, [%4];"
                 : "=r"(r0), "=r"(r1), "=r"(r2), "=r"(r3) : "r"(a));
}
__device__ __forceinline__ void ldsm4t(uint32_t& r0, uint32_t& r1,
                                       uint32_t& r2, uint32_t& r3, uint32_t a) {
    asm volatile("ldmatrix.sync.aligned.m8n8.x4.trans.shared.b16 {%0,%1,%2,%3}, [%4];"
                 : "=r"(r0), "=r"(r1), "=r"(r2), "=r"(r3) : "r"(a));
}
__device__ __forceinline__ void mma16816(float* d, uint32_t a0, uint32_t a1,
                                         uint32_t a2, uint32_t a3,
                                         uint32_t b0, uint32_t b1) {
    asm volatile(
        "mma.sync.aligned.m16n8k16.row.col.f32.f16.f16.f32 "
        "{%0,%1,%2,%3}, {%4,%5,%6,%7}, {%8,%9}, {%0,%1,%2,%3};"
        : "+f"(d[0]), "+f"(d[1]), "+f"(d[2]), "+f"(d[3])
        : "r"(a0), "r"(a1), "r"(a2), "r"(a3), "r"(b0), "r"(b1));
}

// stage X tile (128 rows x 64) into fp16 smem
__device__ __forceinline__ void load_a_tile(const float* __restrict__ X,
                                            __half* As, int row0, int N, int tid) {
    const float4* X4 = (const float4*)(X + (size_t)row0 * C);
#pragma unroll
    for (int i = 0; i < 8; i++) {
        int j = tid + 256 * i;             // 2048 float4
        int r = j >> 4, c = (j & 15) * 4;
        float4 v = make_float4(0.f, 0.f, 0.f, 0.f);
        if (row0 + r < N) v = X4[j];
        *(__half2*)&As[r * AS_STR + c]     = __floats2half2_rn(v.x, v.y);
        *(__half2*)&As[r * AS_STR + c + 2] = __floats2half2_rn(v.z, v.w);
    }
}
__device__ __forceinline__ void load_a_tile(const __half* __restrict__ X,
                                            __half* As, int row0, int N, int tid) {
    const uint4* X8 = (const uint4*)(X + (size_t)row0 * C);
#pragma unroll
    for (int i = 0; i < 4; i++) {
        int j = tid + 256 * i;             // 1024 uint4
        int r = j >> 3, c = (j & 7) * 8;
        uint4 v = make_uint4(0, 0, 0, 0);
        if (row0 + r < N) v = X8[j];
        *(uint4*)&As[r * AS_STR + c] = v;  // byte off r*144+c*2, both 16B-mult
    }
}

template <typename T>
__device__ __forceinline__ void gemm_body(const T* __restrict__ X,
                                          const float* __restrict__ W,
                                          __half* __restrict__ H, int N,
                                          int bid) {
    __shared__ __half As[128 * AS_STR];    // 18.4 KB
    __shared__ __half Wsm[64 * AS_STR];    // 9.2 KB
    int tid  = threadIdx.x;
    int row0 = bid * 128;

    // W fp32 -> fp16 smem
    {
        const float4* W4 = (const float4*)W;
#pragma unroll
        for (int i = 0; i < 4; i++) {
            int j = tid + 256 * i;         // 1024 float4
            float4 v = W4[j];
            int r = j >> 4, c = (j & 15) * 4;
            *(__half2*)&Wsm[r * AS_STR + c]     = __floats2half2_rn(v.x, v.y);
            *(__half2*)&Wsm[r * AS_STR + c + 2] = __floats2half2_rn(v.z, v.w);
        }
    }
    load_a_tile(X, As, row0, N, tid);
    __syncthreads();

    int w    = tid >> 5;
    int lane = tid & 31;
    int R    = w * 16;                     // warp row-tile within block
    int l8   = lane & 7;
    int mb0  = (lane >> 3) & 1;            // matrix-id bit0 -> +8 rows
    int mb1  = (lane >> 4) & 1;            // matrix-id bit1 -> +8 cols

    float d[8][4];
#pragma unroll
    for (int i = 0; i < 8; i++)
#pragma unroll
        for (int j = 0; j < 4; j++) d[i][j] = 0.f;

    uint32_t a_base = (uint32_t)__cvta_generic_to_shared(As);
    uint32_t w_base = (uint32_t)__cvta_generic_to_shared(Wsm);

#pragma unroll
    for (int kk = 0; kk < 4; kk++) {
        uint32_t a0, a1, a2, a3;
        uint32_t aaddr = a_base +
            ((R + mb0 * 8 + l8) * AS_STR + kk * 16 + mb1 * 8) * 2;
        ldsm4(a0, a1, a2, a3, aaddr);
#pragma unroll
        for (int np = 0; np < 4; np++) {
            uint32_t b0, b1, b2, b3;
            uint32_t baddr = w_base +
                ((kk * 16 + mb0 * 8 + l8) * AS_STR + np * 16 + mb1 * 8) * 2;
            ldsm4t(b0, b1, b2, b3, baddr);
            mma16816(d[np * 2],     a0, a1, a2, a3, b0, b1);
            mma16816(d[np * 2 + 1], a0, a1, a2, a3, b2, b3);
        }
    }

    // epilogue: scale by dinv, fp16 store
    int g4 = lane >> 2, t4 = lane & 3;
    int r0g = row0 + R + g4;
    int r1g = r0g + 8;
    float dn0 = (r0g < N) ? g_dinv[r0g] : 0.f;
    float dn1 = (r1g < N) ? g_dinv[r1g] : 0.f;
#pragma unroll
    for (int nt = 0; nt < 8; nt++) {
        int coff = nt * 8 + t4 * 2;
        if (r0g < N)
            *(__half2*)(H + (size_t)r0g * C + coff) =
                __floats2half2_rn(d[nt][0] * dn0, d[nt][1] * dn0);
        if (r1g < N)
            *(__half2*)(H + (size_t)r1g * C + coff) =
                __floats2half2_rn(d[nt][2] * dn1, d[nt][3] * dn1);
    }
}

__global__ void __launch_bounds__(256) k_gemm_h(const __half* __restrict__ X,
                                                const float* __restrict__ W,
                                                __half* __restrict__ H, int N) {
    gemm_body<__half>(X, W, H, N, blockIdx.x);
}

__global__ void __launch_bounds__(256) k_gemm_scatter(
        const float* __restrict__ X, const float* __restrict__ W,
        __half* __restrict__ H, int N,
        const void* __restrict__ eiv, int E, int SB) {
    if (blockIdx.x < SB) scatter_body(eiv, E, blockIdx.x);
    else                 gemm_body<float>(X, W, H, N, blockIdx.x - SB);
}

// ---------------- aggregation: 4 nodes per warp (8-lane groups) -------------
template <bool HALF_OUT, bool RELU>
__global__ void __launch_bounds__(256) k_agg(const __half* __restrict__ H,
                                             const float* __restrict__ bias,
                                             void* __restrict__ outv, int N) {
    const unsigned F = 0xffffffffu;
    int gid  = blockIdx.x * blockDim.x + threadIdx.x;
    int warp = gid >> 5;
    int lane = gid & 31;
    int g    = lane >> 3;
    int l8   = lane & 7;
    int n    = warp * 4 + g;
    bool act = (n < N);

    int beg = 0, end = 0;
    if (act) { beg = g_rowptr[n]; end = g_rowptr[n + 1]; }
    int len = end - beg;
    int lm  = len;
    lm = max(lm, __shfl_xor_sync(F, lm, 8));
    lm = max(lm, __shfl_xor_sync(F, lm, 16));

    float a0=0.f,a1=0.f,a2=0.f,a3=0.f,a4=0.f,a5=0.f,a6=0.f,a7=0.f;
    for (int off = 0; off < lm; off += 8) {
        int cnt = min(len - off, 8);
        int sp  = (l8 < cnt) ? g_col[beg + off + l8] : 0;
        int cm  = cnt;
        cm = max(cm, __shfl_xor_sync(F, cm, 8));
        cm = max(cm, __shfl_xor_sync(F, cm, 16));
#pragma unroll 4
        for (int j = 0; j < cm; j++) {
            int   s = __shfl_sync(F, sp, (g << 3) + j);
            float m = (j < cnt) ? 1.f : 0.f;
            uint4 v = *(const uint4*)(H + (size_t)s * C + l8 * 8);
            float2 f0 = __half22float2(*(__half2*)&v.x);
            float2 f1 = __half22float2(*(__half2*)&v.y);
            float2 f2 = __half22float2(*(__half2*)&v.z);
            float2 f3 = __half22float2(*(__half2*)&v.w);
            a0 += m * f0.x; a1 += m * f0.y; a2 += m * f1.x; a3 += m * f1.y;
            a4 += m * f2.x; a5 += m * f2.y; a6 += m * f3.x; a7 += m * f3.y;
        }
    }

    if (act) {
        float dn = g_dinv[n];
        uint4 hv = *(const uint4*)(H + (size_t)n * C + l8 * 8);
        float2 h0 = __half22float2(*(__half2*)&hv.x);
        float2 h1 = __half22float2(*(__half2*)&hv.y);
        float2 h2 = __half22float2(*(__half2*)&hv.z);
        float2 h3 = __half22float2(*(__half2*)&hv.w);
        float4 bA = *(const float4*)(bias + l8 * 8);
        float4 bB = *(const float4*)(bias + l8 * 8 + 4);
        float r0 = dn * (a0 + h0.x) + bA.x;
        float r1 = dn * (a1 + h0.y) + bA.y;
        float r2 = dn * (a2 + h1.x) + bA.z;
        float r3 = dn * (a3 + h1.y) + bA.w;
        float r4 = dn * (a4 + h2.x) + bB.x;
        float r5 = dn * (a5 + h2.y) + bB.y;
        float r6 = dn * (a6 + h3.x) + bB.z;
        float r7 = dn * (a7 + h3.y) + bB.w;
        if (RELU) {
            r0 = fmaxf(r0, 0.f); r1 = fmaxf(r1, 0.f);
            r2 = fmaxf(r2, 0.f); r3 = fmaxf(r3, 0.f);
            r4 = fmaxf(r4, 0.f); r5 = fmaxf(r5, 0.f);
            r6 = fmaxf(r6, 0.f); r7 = fmaxf(r7, 0.f);
        }
        if (HALF_OUT) {
            __half2 o0 = __floats2half2_rn(r0, r1);
            __half2 o1 = __floats2half2_rn(r2, r3);
            __half2 o2 = __floats2half2_rn(r4, r5);
            __half2 o3 = __floats2half2_rn(r6, r7);
            uint4 pk = make_uint4(*(uint32_t*)&o0, *(uint32_t*)&o1,
                                  *(uint32_t*)&o2, *(uint32_t*)&o3);
            *(uint4*)((__half*)outv + (size_t)n * C + l8 * 8) = pk;
        } else {
            float* o = (float*)outv + (size_t)n * C + l8 * 8;
            *(float4*)o       = make_float4(r0, r1, r2, r3);
            *(float4*)(o + 4) = make_float4(r4, r5, r6, r7);
        }
    }
}

// ---------------- launch ----------------------------------------------------
extern "C" void kernel_launch(void* const* d_in, const int* in_sizes, int n_in,
                              void* d_out, int out_size) {
    const float* x   = (const float*)d_in[0];
    const void*  ei  = d_in[1];
    const float* W1  = (const float*)d_in[2];
    const float* b1  = (const float*)d_in[3];
    const float* W2  = (const float*)d_in[4];
    const float* b2  = (const float*)d_in[5];
    float*       out = (float*)d_out;

    int N = in_sizes[0] / C;     // 100000
    int E = in_sizes[1] / 2;     // 1200000

    __half* ha; cudaGetSymbolAddress((void**)&ha, g_ha);
    __half* hb; cudaGetSymbolAddress((void**)&hb, g_hb);

    int CH  = (N + NB_PRE - 1) / NB_PRE;
    int SB  = (E + 255) / 256;
    int GB  = (N + 127) / 128;              // 782 mma-gemm blocks
    int AGB = (N + 31) / 32;

    k_pre<<<NB_PRE, 256>>>(ei, E, N, CH);

    k_gemm_scatter<<<SB + GB, 256>>>(x, W1, ha, N, ei, E, SB);
    k_agg<true, true><<<AGB, 256>>>(ha, b1, hb, N);
    k_gemm_h<<<GB, 256>>>(hb, W2, ha, N);
    k_agg<false, false><<<AGB, 256>>>(ha, b2, out, N);
}

// round 9
// speedup vs baseline: 2.3115x; 1.0580x over previous
#include <cuda_runtime.h>
#include <cuda_fp16.h>
#include <stdint.h>

#define NN 100000
#define EMAX 1200000
#define C 64
#define NB_PRE 444   // 3 blocks/SM on 148 SMs -> co-residency guaranteed

// ---------------- scratch (device globals; no allocation allowed) ----------
__device__ __half g_ha[NN * C];
__device__ __half g_hb[NN * C];
__device__ __half g_w1h[C * C];
__device__ __half g_w2h[C * C];
__device__ float  g_dinv[NN];
__device__ int    g_deg[NN];       // in-degree (self-loop excluded) == CSR len
__device__ int    g_rowptr[NN];    // CSR base (non-monotonic, atomically allocated)
__device__ int    g_cursor[NN];
__device__ int    g_col[EMAX];
__device__ int    g_total;
__device__ int    g_is64;
__device__ int    g_barA[8];
__device__ int    g_barD[8];

// ---------------- device-wide barrier (self-resetting, replay-safe) ---------
__device__ __forceinline__ void grid_barrier(int slot, int nb) {
    __syncthreads();
    if (threadIdx.x == 0) {
        __threadfence();
        atomicAdd(&g_barA[slot], 1);
        while (atomicAdd(&g_barA[slot], 0) < nb) __nanosleep(64);
        __threadfence();
        int d = atomicAdd(&g_barD[slot], 1);
        if (d == nb - 1) {
            atomicExch(&g_barA[slot], 0);
            atomicExch(&g_barD[slot], 0);
        }
    }
    __syncthreads();
}

__device__ __forceinline__ int blk_excl_scan256(int v, int* tot) {
    __shared__ int ws[8];
    int lane = threadIdx.x & 31, w = threadIdx.x >> 5;
    int x = v;
#pragma unroll
    for (int o = 1; o < 32; o <<= 1) {
        int u = __shfl_up_sync(0xffffffffu, x, o);
        if (lane >= o) x += u;
    }
    if (lane == 31) ws[w] = x;
    __syncthreads();
    if (w == 0) {
        int s = (lane < 8) ? ws[lane] : 0;
#pragma unroll
        for (int o = 1; o < 8; o <<= 1) {
            int u = __shfl_up_sync(0xffffffffu, s, o);
            if (lane >= o) s += u;
        }
        if (lane < 8) ws[lane] = s;
    }
    __syncthreads();
    *tot = ws[7];
    int excl = x - v + (w ? ws[w - 1] : 0);
    __syncthreads();
    return excl;
}

__device__ __forceinline__ int load_idx(const void* eiv, long long pos) {
    if (g_is64) return (int)((const long long*)eiv)[pos];
    return ((const int*)eiv)[pos];
}

// ---------------- fused persistent preprocessing (3 phases, 2 barriers) -----
// P0 zero deg + counter + probe | P1 hist | P2 block scan + atomic base ->
// rowptr/cursor/dinv; blocks 0,1 also convert W1/W2 to fp16.
__global__ void __launch_bounds__(256, 4) k_pre(const void* __restrict__ eiv,
                                                const float* __restrict__ W1,
                                                const float* __restrict__ W2,
                                                int E, int N, int CH) {
    int b = blockIdx.x, t = threadIdx.x;
    const int NB = gridDim.x;

    for (int i = b * 256 + t; i < N; i += NB * 256) g_deg[i] = 0;
    if (b == 0) {
        __shared__ int anz;
        if (t == 0) { anz = 0; g_total = 0; }
        __syncthreads();
        int e = t * (E / 256);
        if (((const int*)eiv)[2 * e + 1] != 0) anz = 1;
        __syncthreads();
        if (t == 0) g_is64 = (anz == 0);
    }
    grid_barrier(0, NB);

    for (int e = b * 256 + t; e < E; e += NB * 256) {
        int d = load_idx(eiv, (long long)E + e);
        if ((unsigned)d < (unsigned)NN) atomicAdd(&g_deg[d], 1);
    }
    grid_barrier(1, NB);

    // P2: per-block exclusive scan + one atomic base per block
    {
        __shared__ int base;
        int i = b * CH + t;
        bool ok = (t < CH && i < N);
        int v = ok ? g_deg[i] : 0;
        int tot;
        int ex = blk_excl_scan256(v, &tot);
        if (t == 0) base = atomicAdd(&g_total, tot);
        __syncthreads();
        if (ok) {
            int r = base + ex;
            g_rowptr[i] = r;
            g_cursor[i] = r;
            g_dinv[i]   = rsqrtf((float)(v + 1));
        }
    }
    // W fp32 -> fp16 (blocks 0,1; no barrier needed — used next launch)
    if (b < 2) {
        const float* Wsrc = b ? W2 : W1;
        __half* Wdst = b ? g_w2h : g_w1h;
        const float4* W4 = (const float4*)Wsrc;
#pragma unroll
        for (int i = 0; i < 4; i++) {
            int j = t + 256 * i;           // 1024 float4
            float4 v = W4[j];
            __half2 h0 = __floats2half2_rn(v.x, v.y);
            __half2 h1 = __floats2half2_rn(v.z, v.w);
            *(uint2*)&Wdst[j * 4] = make_uint2(*(uint32_t*)&h0, *(uint32_t*)&h1);
        }
    }
}

__device__ __forceinline__ void scatter_body(const void* eiv, int E, int bid) {
    int e = bid * 256 + threadIdx.x;
    if (e < E) {
        int s = load_idx(eiv, e);
        int d = load_idx(eiv, (long long)E + e);
        if ((unsigned)s < (unsigned)NN && (unsigned)d < (unsigned)NN) {
            int p = atomicAdd(&g_cursor[d], 1);
            g_col[p] = s;
        }
    }
}

// ---------------- tensor-core GEMM (mma.sync HMMA) ---------------------------
#define AS_STR 72

__device__ __forceinline__ void ldsm4(uint32_t& r0, uint32_t& r1,
                                      uint32_t& r2, uint32_t& r3, uint32_t a) {
    asm volatile("ldmatrix.sync.aligned.m8n8.x4.shared.b16 {%0,%1,%2,%3}, [%4];"
                 : "=r"(r0), "=r"(r1), "=r"(r2), "=r"(r3) : "r"(a));
}
__device__ __forceinline__ void ldsm4t(uint32_t& r0, uint32_t& r1,
                                       uint32_t& r2, uint32_t& r3, uint32_t a) {
    asm volatile("ldmatrix.sync.aligned.m8n8.x4.trans.shared.b16 {%0,%1,%2,%3}, [%4];"
                 : "=r"(r0), "=r"(r1), "=r"(r2), "=r"(r3) : "r"(a));
}
__device__ __forceinline__ void mma16816(float* d, uint32_t a0, uint32_t a1,
                                         uint32_t a2, uint32_t a3,
                                         uint32_t b0, uint32_t b1) {
    asm volatile(
        "mma.sync.aligned.m16n8k16.row.col.f32.f16.f16.f32 "
        "{%0,%1,%2,%3}, {%4,%5,%6,%7}, {%8,%9}, {%0,%1,%2,%3};"
        : "+f"(d[0]), "+f"(d[1]), "+f"(d[2]), "+f"(d[3])
        : "r"(a0), "r"(a1), "r"(a2), "r"(a3), "r"(b0), "r"(b1));
}

__device__ __forceinline__ void load_a_tile(const float* __restrict__ X,
                                            __half* As, int row0, int N, int tid) {
    const float4* X4 = (const float4*)(X + (size_t)row0 * C);
#pragma unroll
    for (int i = 0; i < 8; i++) {
        int j = tid + 256 * i;
        int r = j >> 4, c = (j & 15) * 4;
        float4 v = make_float4(0.f, 0.f, 0.f, 0.f);
        if (row0 + r < N) v = X4[j];
        *(__half2*)&As[r * AS_STR + c]     = __floats2half2_rn(v.x, v.y);
        *(__half2*)&As[r * AS_STR + c + 2] = __floats2half2_rn(v.z, v.w);
    }
}
__device__ __forceinline__ void load_a_tile(const __half* __restrict__ X,
                                            __half* As, int row0, int N, int tid) {
    const uint4* X8 = (const uint4*)(X + (size_t)row0 * C);
#pragma unroll
    for (int i = 0; i < 4; i++) {
        int j = tid + 256 * i;
        int r = j >> 3, c = (j & 7) * 8;
        uint4 v = make_uint4(0, 0, 0, 0);
        if (row0 + r < N) v = X8[j];
        *(uint4*)&As[r * AS_STR + c] = v;
    }
}

template <typename T>
__device__ __forceinline__ void gemm_body(const T* __restrict__ X,
                                          const __half* __restrict__ Wh,
                                          __half* __restrict__ H, int N,
                                          int bid) {
    __shared__ __half As[128 * AS_STR];
    __shared__ __half Wsm[64 * AS_STR];
    int tid  = threadIdx.x;
    int row0 = bid * 128;

    // W fp16 -> smem (512 uint4)
    {
        const uint4* W8 = (const uint4*)Wh;
#pragma unroll
        for (int i = 0; i < 2; i++) {
            int j = tid + 256 * i;
            int r = j >> 3, c = (j & 7) * 8;
            *(uint4*)&Wsm[r * AS_STR + c] = W8[j];
        }
    }
    load_a_tile(X, As, row0, N, tid);
    __syncthreads();

    int w    = tid >> 5;
    int lane = tid & 31;
    int R    = w * 16;
    int l8   = lane & 7;
    int mb0  = (lane >> 3) & 1;
    int mb1  = (lane >> 4) & 1;

    float d[8][4];
#pragma unroll
    for (int i = 0; i < 8; i++)
#pragma unroll
        for (int j = 0; j < 4; j++) d[i][j] = 0.f;

    uint32_t a_base = (uint32_t)__cvta_generic_to_shared(As);
    uint32_t w_base = (uint32_t)__cvta_generic_to_shared(Wsm);

#pragma unroll
    for (int kk = 0; kk < 4; kk++) {
        uint32_t a0, a1, a2, a3;
        uint32_t aaddr = a_base +
            ((R + mb0 * 8 + l8) * AS_STR + kk * 16 + mb1 * 8) * 2;
        ldsm4(a0, a1, a2, a3, aaddr);
#pragma unroll
        for (int np = 0; np < 4; np++) {
            uint32_t b0, b1, b2, b3;
            uint32_t baddr = w_base +
                ((kk * 16 + mb0 * 8 + l8) * AS_STR + np * 16 + mb1 * 8) * 2;
            ldsm4t(b0, b1, b2, b3, baddr);
            mma16816(d[np * 2],     a0, a1, a2, a3, b0, b1);
            mma16816(d[np * 2 + 1], a0, a1, a2, a3, b2, b3);
        }
    }

    int g4 = lane >> 2, t4 = lane & 3;
    int r0g = row0 + R + g4;
    int r1g = r0g + 8;
    float dn0 = (r0g < N) ? g_dinv[r0g] : 0.f;
    float dn1 = (r1g < N) ? g_dinv[r1g] : 0.f;
#pragma unroll
    for (int nt = 0; nt < 8; nt++) {
        int coff = nt * 8 + t4 * 2;
        if (r0g < N)
            *(__half2*)(H + (size_t)r0g * C + coff) =
                __floats2half2_rn(d[nt][0] * dn0, d[nt][1] * dn0);
        if (r1g < N)
            *(__half2*)(H + (size_t)r1g * C + coff) =
                __floats2half2_rn(d[nt][2] * dn1, d[nt][3] * dn1);
    }
}

__global__ void __launch_bounds__(256) k_gemm_h(const __half* __restrict__ X,
                                                const __half* __restrict__ Wh,
                                                __half* __restrict__ H, int N) {
    gemm_body<__half>(X, Wh, H, N, blockIdx.x);
}

__global__ void __launch_bounds__(256) k_gemm_scatter(
        const float* __restrict__ X, const __half* __restrict__ Wh,
        __half* __restrict__ H, int N,
        const void* __restrict__ eiv, int E, int SB) {
    if (blockIdx.x < SB) scatter_body(eiv, E, blockIdx.x);
    else                 gemm_body<float>(X, Wh, H, N, blockIdx.x - SB);
}

// ---------------- aggregation: 4 nodes per warp (8-lane groups) -------------
// out[n] = dinv[n] * (sum_{s in in(n)} H[s] + H[n]) + b ; len = g_deg[n].
template <bool HALF_OUT, bool RELU>
__global__ void __launch_bounds__(256) k_agg(const __half* __restrict__ H,
                                             const float* __restrict__ bias,
                                             void* __restrict__ outv, int N) {
    const unsigned F = 0xffffffffu;
    int gid  = blockIdx.x * blockDim.x + threadIdx.x;
    int warp = gid >> 5;
    int lane = gid & 31;
    int g    = lane >> 3;
    int l8   = lane & 7;
    int n    = warp * 4 + g;
    bool act = (n < N);

    int beg = 0, len = 0;
    if (act) { beg = g_rowptr[n]; len = g_deg[n]; }
    int lm = len;
    lm = max(lm, __shfl_xor_sync(F, lm, 8));
    lm = max(lm, __shfl_xor_sync(F, lm, 16));

    float a0=0.f,a1=0.f,a2=0.f,a3=0.f,a4=0.f,a5=0.f,a6=0.f,a7=0.f;
    for (int off = 0; off < lm; off += 8) {
        int cnt = min(len - off, 8);
        int sp  = (l8 < cnt) ? g_col[beg + off + l8] : 0;
        int cm  = cnt;
        cm = max(cm, __shfl_xor_sync(F, cm, 8));
        cm = max(cm, __shfl_xor_sync(F, cm, 16));
#pragma unroll 4
        for (int j = 0; j < cm; j++) {
            int   s = __shfl_sync(F, sp, (g << 3) + j);
            float m = (j < cnt) ? 1.f : 0.f;
            uint4 v = *(const uint4*)(H + (size_t)s * C + l8 * 8);
            float2 f0 = __half22float2(*(__half2*)&v.x);
            float2 f1 = __half22float2(*(__half2*)&v.y);
            float2 f2 = __half22float2(*(__half2*)&v.z);
            float2 f3 = __half22float2(*(__half2*)&v.w);
            a0 += m * f0.x; a1 += m * f0.y; a2 += m * f1.x; a3 += m * f1.y;
            a4 += m * f2.x; a5 += m * f2.y; a6 += m * f3.x; a7 += m * f3.y;
        }
    }

    if (act) {
        float dn = g_dinv[n];
        uint4 hv = *(const uint4*)(H + (size_t)n * C + l8 * 8);
        float2 h0 = __half22float2(*(__half2*)&hv.x);
        float2 h1 = __half22float2(*(__half2*)&hv.y);
        float2 h2 = __half22float2(*(__half2*)&hv.z);
        float2 h3 = __half22float2(*(__half2*)&hv.w);
        float4 bA = *(const float4*)(bias + l8 * 8);
        float4 bB = *(const float4*)(bias + l8 * 8 + 4);
        float r0 = dn * (a0 + h0.x) + bA.x;
        float r1 = dn * (a1 + h0.y) + bA.y;
        float r2 = dn * (a2 + h1.x) + bA.z;
        float r3 = dn * (a3 + h1.y) + bA.w;
        float r4 = dn * (a4 + h2.x) + bB.x;
        float r5 = dn * (a5 + h2.y) + bB.y;
        float r6 = dn * (a6 + h3.x) + bB.z;
        float r7 = dn * (a7 + h3.y) + bB.w;
        if (RELU) {
            r0 = fmaxf(r0, 0.f); r1 = fmaxf(r1, 0.f);
            r2 = fmaxf(r2, 0.f); r3 = fmaxf(r3, 0.f);
            r4 = fmaxf(r4, 0.f); r5 = fmaxf(r5, 0.f);
            r6 = fmaxf(r6, 0.f); r7 = fmaxf(r7, 0.f);
        }
        if (HALF_OUT) {
            __half2 o0 = __floats2half2_rn(r0, r1);
            __half2 o1 = __floats2half2_rn(r2, r3);
            __half2 o2 = __floats2half2_rn(r4, r5);
            __half2 o3 = __floats2half2_rn(r6, r7);
            uint4 pk = make_uint4(*(uint32_t*)&o0, *(uint32_t*)&o1,
                                  *(uint32_t*)&o2, *(uint32_t*)&o3);
            *(uint4*)((__half*)outv + (size_t)n * C + l8 * 8) = pk;
        } else {
            float* o = (float*)outv + (size_t)n * C + l8 * 8;
            *(float4*)o       = make_float4(r0, r1, r2, r3);
            *(float4*)(o + 4) = make_float4(r4, r5, r6, r7);
        }
    }
}

// ---------------- launch ----------------------------------------------------
extern "C" void kernel_launch(void* const* d_in, const int* in_sizes, int n_in,
                              void* d_out, int out_size) {
    const float* x   = (const float*)d_in[0];
    const void*  ei  = d_in[1];
    const float* W1  = (const float*)d_in[2];
    const float* W2  = (const float*)d_in[4];
    const float* b1  = (const float*)d_in[3];
    const float* b2  = (const float*)d_in[5];
    float*       out = (float*)d_out;

    int N = in_sizes[0] / C;     // 100000
    int E = in_sizes[1] / 2;     // 1200000

    __half* ha;  cudaGetSymbolAddress((void**)&ha, g_ha);
    __half* hb;  cudaGetSymbolAddress((void**)&hb, g_hb);
    __half* w1h; cudaGetSymbolAddress((void**)&w1h, g_w1h);
    __half* w2h; cudaGetSymbolAddress((void**)&w2h, g_w2h);

    int CH  = (N + NB_PRE - 1) / NB_PRE;
    int SB  = (E + 255) / 256;
    int GB  = (N + 127) / 128;
    int AGB = (N + 31) / 32;

    k_pre<<<NB_PRE, 256>>>(ei, W1, W2, E, N, CH);

    k_gemm_scatter<<<SB + GB, 256>>>(x, w1h, ha, N, ei, E, SB);
    k_agg<true, true><<<AGB, 256>>>(ha, b1, hb, N);
    k_gemm_h<<<GB, 256>>>(hb, w2h, ha, N);
    k_agg<false, false><<<AGB, 256>>>(ha, b2, out, N);
}